// round 14
// baseline (speedup 1.0000x reference)
#include <cuda_runtime.h>
#include <cuda_fp16.h>
#include <math.h>
#include <stdint.h>

// ---------------- problem constants ----------------
#define Bq 8
#define Sq 1024
#define Dq 1024
#define DAq 256
#define Hq 16
#define HDq 64
#define Rq 32
#define Mtok (Bq*Sq)   // 8192
#define NCAT (DAq + 3*Dq)   // 3328

// ---------------- scratch (device globals; no allocation) ----------------
__device__ __half g_xh[Mtok*Dq];                  // fp16 x
__device__ float g_WuT [Dq*Dq];
__device__ float g_WkselT[DAq*Dq];
__device__ __half g_Wcat_h[NCAT*Dq];              // [qsel|q|k|v] transposed fp16
__device__ __half g_WoT_h[Dq*Dq];
__device__ float g_pooled[Bq*Rq*Dq];
__device__ float g_root  [Bq*Rq*Dq];
__device__ float g_ksel  [Bq*Rq*DAq];
__device__ float g_part[4*256*1024];
__device__ float g_qsel  [Mtok*DAq];
__device__ unsigned char g_mask[Mtok*Rq];
__device__ __half g_q [Mtok*Dq];                  // [B,H,S,64] fp16
__device__ __half g_k [Mtok*Dq];
__device__ __half g_v [Mtok*Dq];
__device__ __half g_ctx_h[Mtok*Dq];               // [B,S,D] fp16

// ---------------- helpers ----------------
__device__ __forceinline__ float rna_tf32(float x) {
    uint32_t r; asm("cvt.rna.tf32.f32 %0, %1;" : "=r"(r) : "f"(x));
    return __uint_as_float(r);
}
__device__ __forceinline__ uint32_t smem_u32(const void* p) {
    uint32_t a;
    asm("{ .reg .u64 t; cvta.to.shared.u64 t, %1; cvt.u32.u64 %0, t; }" : "=r"(a) : "l"(p));
    return a;
}

#define CP16(dst, src) \
    asm volatile("cp.async.cg.shared.global [%0], [%1], 16;" :: "r"(dst), "l"(src))
#define CPCOMMIT() asm volatile("cp.async.commit_group;")
#define CPWAIT(n)  asm volatile("cp.async.wait_group %0;" :: "n"(n))

#define LDSM4(r0, r1, r2, r3, addr) \
    asm volatile("ldmatrix.sync.aligned.m8n8.x4.shared.b16 {%0,%1,%2,%3}, [%4];" \
        : "=r"(r0), "=r"(r1), "=r"(r2), "=r"(r3) : "r"(addr))

__device__ __forceinline__ void mma_tf32(float c[4], const uint32_t a[4], const uint32_t b[2]) {
    asm volatile(
        "mma.sync.aligned.m16n8k8.row.col.f32.tf32.tf32.f32 "
        "{%0,%1,%2,%3}, {%4,%5,%6,%7}, {%8,%9}, {%0,%1,%2,%3};"
        : "+f"(c[0]), "+f"(c[1]), "+f"(c[2]), "+f"(c[3])
        : "r"(a[0]), "r"(a[1]), "r"(a[2]), "r"(a[3]), "r"(b[0]), "r"(b[1]));
}
__device__ __forceinline__ void mma_f16(float c[4], const uint32_t a[4], const uint32_t b[2]) {
    asm volatile(
        "mma.sync.aligned.m16n8k16.row.col.f32.f16.f16.f32 "
        "{%0,%1,%2,%3}, {%4,%5,%6,%7}, {%8,%9}, {%0,%1,%2,%3};"
        : "+f"(c[0]), "+f"(c[1]), "+f"(c[2]), "+f"(c[3])
        : "r"(a[0]), "r"(a[1]), "r"(a[2]), "r"(a[3]), "r"(b[0]), "r"(b[1]));
}

// ---------------- prep kernels ----------------
__global__ void round_copy_kernel(const float4* __restrict__ in, __half2* __restrict__ xh, int n4) {
    int i = blockIdx.x * blockDim.x + threadIdx.x;
    if (i < n4) {
        float4 v = in[i];
        xh[2 * i]     = __floats2half2_rn(v.x, v.y);
        xh[2 * i + 1] = __floats2half2_rn(v.z, v.w);
    }
}

__global__ void transpose_all_kernel(
    const float* __restrict__ Wq_sel, const float* __restrict__ Wq,
    const float* __restrict__ Wk, const float* __restrict__ Wv,
    const float* __restrict__ Wu, const float* __restrict__ Wo,
    const float* __restrict__ Wk_sel,
    __half* __restrict__ Wcat_h, float* __restrict__ WuT,
    __half* __restrict__ WoT_h, float* __restrict__ WkselT)
{
    __shared__ float t[32][33];
    int tix = blockIdx.x;
    const float* W; int Ndim, seg;
    if (tix < 256)       { seg = 0; W = Wq_sel; Ndim = DAq; }
    else if (tix < 1280) { seg = 1; tix -= 256;  W = Wq; Ndim = Dq; }
    else if (tix < 2304) { seg = 2; tix -= 1280; W = Wk; Ndim = Dq; }
    else if (tix < 3328) { seg = 3; tix -= 2304; W = Wv; Ndim = Dq; }
    else if (tix < 4352) { seg = 4; tix -= 3328; W = Wu; Ndim = Dq; }
    else if (tix < 5376) { seg = 5; tix -= 4352; W = Wo; Ndim = Dq; }
    else                 { seg = 6; tix -= 5376; W = Wk_sel; Ndim = DAq; }
    int ntile = Ndim >> 5;
    int n0 = (tix % ntile) * 32, k0 = (tix / ntile) * 32;
    int tx = threadIdx.x, ty = threadIdx.y;
    #pragma unroll
    for (int i = 0; i < 32; i += 8)
        t[ty + i][tx] = W[(size_t)(k0 + ty + i) * Ndim + n0 + tx];
    __syncthreads();
    if (seg <= 3) {
        size_t base = (seg == 0) ? 0 : (size_t)(DAq + (seg - 1) * Dq) * Dq;
        __half* dst = Wcat_h + base;
        #pragma unroll
        for (int i = 0; i < 32; i += 8)
            dst[(size_t)(n0 + ty + i) * Dq + k0 + tx] = __float2half_rn(t[tx][ty + i]);
    } else if (seg == 5) {
        #pragma unroll
        for (int i = 0; i < 32; i += 8)
            WoT_h[(size_t)(n0 + ty + i) * Dq + k0 + tx] = __float2half_rn(t[tx][ty + i]);
    } else {
        float* dst = (seg == 4) ? WuT : WkselT;
        #pragma unroll
        for (int i = 0; i < 32; i += 8)
            dst[(size_t)(n0 + ty + i) * Dq + k0 + tx] = rna_tf32(t[tx][ty + i]);
    }
}

__global__ void pool_kernel(const float* __restrict__ x, float* __restrict__ pooled) {
    int br = blockIdx.x;
    const float* base = x + (size_t)br * 32 * Dq;
    int d4 = threadIdx.x;
    float4 acc = make_float4(0.f, 0.f, 0.f, 0.f);
    #pragma unroll 4
    for (int i = 0; i < 32; i++) {
        float4 v = *(const float4*)(base + (size_t)i * Dq + d4 * 4);
        acc.x += v.x; acc.y += v.y; acc.z += v.z; acc.w += v.w;
    }
    const float s = 1.0f / 32.0f;
    acc.x = rna_tf32(acc.x * s); acc.y = rna_tf32(acc.y * s);
    acc.z = rna_tf32(acc.z * s); acc.w = rna_tf32(acc.w * s);
    *(float4*)(pooled + (size_t)br * Dq + d4 * 4) = acc;
}

// ---------------- fp16 mma.sync GEMM: 128x128, 256 thr, GBK=64 ----------------
#define GBM 128
#define GBN 128
#define GBK 32
#define GBKB 64
#define ROWB 144
#define OP_H_BYTES (128 * ROWB)
#define STAGE_H_BYTES (2 * OP_H_BYTES)
#define SM_GEMM_BYTES (2 * STAGE_H_BYTES) // 73728

__global__ __launch_bounds__(256, 2)
void mma_gemm_h(const __half* __restrict__ A, const __half* __restrict__ Bt,
                float* __restrict__ C, int M, int N, int Kd,
                int mode, const float* __restrict__ resid,
                __half* __restrict__ pq, __half* __restrict__ pk, __half* __restrict__ pv)
{
    extern __shared__ float smf[];
    int tid = threadIdx.x;
    int wid = tid >> 5, lane = tid & 31;
    int warp_row = wid & 1;
    int warp_col = wid >> 1;
    int gr = lane >> 2, gc = lane & 3;
    int bm = blockIdx.y * GBM;
    int bn = blockIdx.x * GBN;

    int sel = lane >> 3, l8 = lane & 7;
    int a_row_off = (sel & 1) * 8 + l8;
    int a_col16 = (sel >> 1) * 16;
    int b_row_off = (sel >> 1) * 8 + l8;
    int b_col16 = (sel & 1) * 16;

    float c[4][4][4];
    #pragma unroll
    for (int f = 0; f < 4; f++)
        #pragma unroll
        for (int g = 0; g < 4; g++)
            #pragma unroll
            for (int i = 0; i < 4; i++) c[f][g][i] = 0.f;

    uint32_t sbase = smem_u32(smf);
    const int NK = Kd / GBKB;

    auto load_stage = [&](int p, int k0) {
        uint32_t Abase = sbase + (uint32_t)(p * STAGE_H_BYTES);
        uint32_t Bbase = Abase + OP_H_BYTES;
        #pragma unroll
        for (int j = 0; j < 4; j++) {
            int idx = tid + j * 256;
            int row = idx >> 3, kc = idx & 7;
            CP16(Abase + (uint32_t)(row * ROWB + kc * 16),
                 A + (size_t)(bm + row) * Kd + k0 + kc * 8);
        }
        #pragma unroll
        for (int j = 0; j < 4; j++) {
            int idx = tid + j * 256;
            int row = idx >> 3, kc = idx & 7;
            CP16(Bbase + (uint32_t)(row * ROWB + kc * 16),
                 Bt + (size_t)(bn + row) * Kd + k0 + kc * 8);
        }
    };

    load_stage(0, 0);
    CPCOMMIT();

    for (int ks = 0; ks < NK; ks++) {
        int p = ks & 1;
        if (ks + 1 < NK) {
            load_stage(p ^ 1, (ks + 1) * GBKB);
            CPCOMMIT();
            CPWAIT(1);
        } else {
            CPWAIT(0);
        }
        __syncthreads();

        uint32_t As = sbase + (uint32_t)(p * STAGE_H_BYTES);
        uint32_t Bs = As + OP_H_BYTES;
        uint32_t aAddr = As + (uint32_t)((warp_row * 64 + a_row_off) * ROWB + a_col16);
        uint32_t bAddr = Bs + (uint32_t)((warp_col * 32 + b_row_off) * ROWB + b_col16);

        #pragma unroll
        for (int kk = 0; kk < 4; kk++) {
            uint32_t a[4][4], b[4][2];
            #pragma unroll
            for (int f = 0; f < 4; f++)
                LDSM4(a[f][0], a[f][1], a[f][2], a[f][3],
                      aAddr + (uint32_t)(f * 16 * ROWB + kk * 32));
            #pragma unroll
            for (int gp = 0; gp < 2; gp++)
                LDSM4(b[2*gp][0], b[2*gp][1], b[2*gp+1][0], b[2*gp+1][1],
                      bAddr + (uint32_t)(gp * 16 * ROWB + kk * 32));
            #pragma unroll
            for (int f = 0; f < 4; f++)
                #pragma unroll
                for (int g = 0; g < 4; g++)
                    mma_f16(c[f][g], a[f], b[g]);
        }
        __syncthreads();
    }

    float* stg = smf;
    #pragma unroll
    for (int f = 0; f < 4; f++)
        #pragma unroll
        for (int g = 0; g < 4; g++) {
            int r0 = warp_row * 64 + f * 16 + gr;
            int c0 = warp_col * 32 + g * 8 + 2 * gc;
            stg[r0 * 132 + c0]           = c[f][g][0];
            stg[r0 * 132 + c0 + 1]       = c[f][g][1];
            stg[(r0 + 8) * 132 + c0]     = c[f][g][2];
            stg[(r0 + 8) * 132 + c0 + 1] = c[f][g][3];
        }
    __syncthreads();

    int ccol = (tid & 31) * 4;
    #pragma unroll 4
    for (int rr = 0; rr < 16; rr++) {
        int r = (tid >> 5) + rr * 8;
        float4 v;
        v.x = stg[r * 132 + ccol + 0];
        v.y = stg[r * 132 + ccol + 1];
        v.z = stg[r * 132 + ccol + 2];
        v.w = stg[r * 132 + ccol + 3];
        int m = bm + r;
        int n = bn + ccol;
        if (mode == 2) {
            float4 rv = *(const float4*)(resid + (size_t)m * N + n);
            v.x += rv.x; v.y += rv.y; v.z += rv.z; v.w += rv.w;
            *(float4*)(C + (size_t)m * N + n) = v;
        } else {
            if (n < DAq) {
                *(float4*)(C + (size_t)m * DAq + n) = v;
            } else {
                int n2 = n - DAq;
                int proj = n2 >> 10, nn = n2 & 1023;
                int h = nn >> 6, hd = nn & 63;
                int b = m >> 10, s = m & 1023;
                __half* P = (proj == 0) ? pq : (proj == 1) ? pk : pv;
                __half2 h01 = __floats2half2_rn(v.x, v.y);
                __half2 h23 = __floats2half2_rn(v.z, v.w);
                uint2 u = make_uint2(*(uint32_t*)&h01, *(uint32_t*)&h23);
                *(uint2*)(P + (((size_t)(b * Hq + h)) * Sq + s) * HDq + hd) = u;
            }
        }
    }
}

// ---------------- split-K small GEMM (tf32, unchanged) ----------------
#define SKLDT 36
#define SK_STAGE (128 * SKLDT)

__global__ __launch_bounds__(128)
void mma_gemm_sk(const float* __restrict__ A, const float* __restrict__ Bt,
                 float* __restrict__ Cpart, int M, int N, int Kd)
{
    __shared__ float smf[2 * SK_STAGE];
    int tid = threadIdx.x;
    int wid = tid >> 5, lane = tid & 31;
    int warp_row = wid & 1;
    int warp_col = wid >> 1;
    int gr = lane >> 2, gc = lane & 3;
    int bm = blockIdx.y * 64;
    int bn = blockIdx.x * 64;
    int kslice = Kd >> 2;
    int kbase = blockIdx.z * kslice;

    int sel = lane >> 3, l8 = lane & 7;
    int a_row_off = (sel & 1) * 8 + l8;
    int a_col_off = (sel >> 1) * 4;
    int b_row_off = (sel >> 1) * 8 + l8;
    int b_col_off = (sel & 1) * 4;

    float c[2][4][4];
    #pragma unroll
    for (int f = 0; f < 2; f++)
        #pragma unroll
        for (int g = 0; g < 4; g++)
            #pragma unroll
            for (int i = 0; i < 4; i++) c[f][g][i] = 0.f;

    uint32_t sbase = smem_u32(smf);
    const int NK = kslice / GBK;

    auto load_stage = [&](int p, int k0) {
        uint32_t Abase = sbase + (uint32_t)(p * SK_STAGE) * 4;
        uint32_t Bbase = Abase + (uint32_t)(64 * SKLDT) * 4;
        #pragma unroll
        for (int j = 0; j < 4; j++) {
            int idx = tid + j * 128;
            int row = idx >> 3, kc = idx & 7;
            CP16(Abase + (uint32_t)(row * SKLDT + kc * 4) * 4,
                 A + (size_t)(bm + row) * Kd + k0 + kc * 4);
        }
        #pragma unroll
        for (int j = 0; j < 4; j++) {
            int idx = tid + j * 128;
            int row = idx >> 3, kc = idx & 7;
            CP16(Bbase + (uint32_t)(row * SKLDT + kc * 4) * 4,
                 Bt + (size_t)(bn + row) * Kd + k0 + kc * 4);
        }
    };

    load_stage(0, kbase);
    CPCOMMIT();

    for (int ks = 0; ks < NK; ks++) {
        int p = ks & 1;
        if (ks + 1 < NK) {
            load_stage(p ^ 1, kbase + (ks + 1) * GBK);
            CPCOMMIT();
            CPWAIT(1);
        } else {
            CPWAIT(0);
        }
        __syncthreads();

        uint32_t As = sbase + (uint32_t)(p * SK_STAGE) * 4;
        uint32_t Bs = As + (uint32_t)(64 * SKLDT) * 4;
        uint32_t aAddr = As + (uint32_t)((warp_row * 32 + a_row_off) * SKLDT + a_col_off) * 4;
        uint32_t bAddr = Bs + (uint32_t)((warp_col * 32 + b_row_off) * SKLDT + b_col_off) * 4;

        #pragma unroll
        for (int kk = 0; kk < 4; kk++) {
            uint32_t a[2][4], b[4][2];
            #pragma unroll
            for (int f = 0; f < 2; f++)
                LDSM4(a[f][0], a[f][1], a[f][2], a[f][3],
                      aAddr + (uint32_t)(f * 16 * SKLDT + kk * 8) * 4);
            #pragma unroll
            for (int gp = 0; gp < 2; gp++)
                LDSM4(b[2*gp][0], b[2*gp][1], b[2*gp+1][0], b[2*gp+1][1],
                      bAddr + (uint32_t)(gp * 16 * SKLDT + kk * 8) * 4);
            #pragma unroll
            for (int f = 0; f < 2; f++)
                #pragma unroll
                for (int g = 0; g < 4; g++)
                    mma_tf32(c[f][g], a[f], b[g]);
        }
        __syncthreads();
    }

    float* Cp = Cpart + (size_t)blockIdx.z * M * N;
    #pragma unroll
    for (int f = 0; f < 2; f++)
        #pragma unroll
        for (int g = 0; g < 4; g++) {
            int r0 = bm + warp_row * 32 + f * 16 + gr;
            int c0 = bn + warp_col * 32 + g * 8 + 2 * gc;
            *(float2*)(Cp + (size_t)r0 * N + c0)       = make_float2(c[f][g][0], c[f][g][1]);
            *(float2*)(Cp + (size_t)(r0 + 8) * N + c0) = make_float2(c[f][g][2], c[f][g][3]);
        }
}

__global__ void reduce4_kernel(const float4* __restrict__ part, float4* __restrict__ dst,
                               int n4, int do_round) {
    int i = blockIdx.x * blockDim.x + threadIdx.x;
    if (i >= n4) return;
    float4 a = part[i], b = part[i + n4], cc = part[i + 2 * n4], d = part[i + 3 * n4];
    float4 v = make_float4(a.x + b.x + cc.x + d.x, a.y + b.y + cc.y + d.y,
                           a.z + b.z + cc.z + d.z, a.w + b.w + cc.w + d.w);
    if (do_round) {
        v.x = rna_tf32(v.x); v.y = rna_tf32(v.y); v.z = rna_tf32(v.z); v.w = rna_tf32(v.w);
    }
    dst[i] = v;
}

// ---------------- block selection ----------------
__device__ __forceinline__ float warp_max_f(float v) {
    #pragma unroll
    for (int o = 16; o; o >>= 1) v = fmaxf(v, __shfl_xor_sync(0xffffffffu, v, o));
    return v;
}
__device__ __forceinline__ float warp_sum_f(float v) {
    #pragma unroll
    for (int o = 16; o; o >>= 1) v += __shfl_xor_sync(0xffffffffu, v, o);
    return v;
}

__global__ __launch_bounds__(256) void select_kernel(
    const float* __restrict__ qsel, const float* __restrict__ ksel,
    unsigned char* __restrict__ mask)
{
    __shared__ float ks[Rq][DAq + 1];
    __shared__ float qrow[8][DAq];
    int b = blockIdx.x;
    int s0 = blockIdx.y * 8;
    int warp = threadIdx.x >> 5, lane = threadIdx.x & 31;
    int s = s0 + warp;

    const float* kp = ksel + (size_t)b * Rq * DAq;
    for (int i = threadIdx.x; i < Rq * DAq; i += 256)
        ks[i >> 8][i & 255] = kp[i];
    const float* qp = qsel + ((size_t)b * Sq + s) * DAq;
    for (int d = lane; d < DAq; d += 32) qrow[warp][d] = qp[d];
    __syncthreads();

    float logit = 0.f;
    #pragma unroll 8
    for (int d = 0; d < DAq; d++)
        logit += qrow[warp][d] * ks[lane][d];
    logit *= 0.0625f;

    float mx = warp_max_f(logit);
    float e = expf(logit - mx);
    float sum = warp_sum_f(e);
    float prob = e / sum;
    bool own = (s >> 5) == lane;
    mask[((size_t)b * Sq + s) * Rq + lane] = (prob >= 0.5f || own) ? 1 : 0;
}

// ---------------- tensor-core block-sparse attention ----------------
// grid (B*H, S/32), 256 thr = 8 warps. One warp per needed key-block (round-robin);
// per-warp online softmax over all 32 queries; final smem merge across warps.
__global__ __launch_bounds__(256) void attn_mma_kernel(
    const __half* __restrict__ Q, const __half* __restrict__ K,
    const __half* __restrict__ V, const unsigned char* __restrict__ mask,
    __half* __restrict__ ctx)
{
    __shared__ __half qs[32 * 72];          // Q tile, row stride 72 halves
    __shared__ uint32_t qbits[32];
    __shared__ uint32_t needm_s;
    __shared__ float ws_m[8][32];
    __shared__ float ws_l[8][32];
    __shared__ __half acc_s[8][32][72];     // per-warp partial ctx (fp16), padded

    int bh = blockIdx.x;
    int b = bh >> 4, h = bh & 15;
    int s0 = blockIdx.y * 32;
    int tid = threadIdx.x, warp = tid >> 5, lane = tid & 31;
    int gr = lane >> 2, gc = lane & 3;

    // Q tile -> smem
    {
        int row = tid >> 3, c8 = (tid & 7) * 8;
        uint4 raw = *(const uint4*)(Q + ((size_t)bh * Sq + s0 + row) * HDq + c8);
        *(uint4*)(qs + row * 72 + c8) = raw;
    }
    if (warp == 0) {
        const unsigned char* mrow = mask + ((size_t)b * Sq + s0 + lane) * Rq;
        uint32_t bits = 0;
        #pragma unroll
        for (int r = 0; r < Rq; r++) bits |= (mrow[r] ? 1u : 0u) << r;
        qbits[lane] = bits;
        #pragma unroll
        for (int o = 16; o; o >>= 1) bits |= __shfl_xor_sync(0xffffffffu, bits, o);
        if (lane == 0) needm_s = bits;
    }
    __syncthreads();
    uint32_t need = needm_s;
    // rows owned by this lane: i = 2*mt + hf -> row 16*mt + 8*hf + gr
    uint32_t rowbits[4] = { qbits[gr], qbits[gr + 8], qbits[16 + gr], qbits[24 + gr] };

    float m4[4], l4[4];
    #pragma unroll
    for (int i = 0; i < 4; i++) { m4[i] = -1e30f; l4[i] = 0.f; }
    float acc[2][8][4];
    #pragma unroll
    for (int mt = 0; mt < 2; mt++)
        #pragma unroll
        for (int nt = 0; nt < 8; nt++)
            #pragma unroll
            for (int j = 0; j < 4; j++) acc[mt][nt][j] = 0.f;

    const __half* Kb = K + (size_t)bh * Sq * HDq;
    const __half* Vb = V + (size_t)bh * Sq * HDq;

    int idx = 0;
    for (int r = 0; r < 32; r++) {
        if (!((need >> r) & 1u)) continue;
        if ((idx++ & 7) != warp) continue;
        const __half* Kt = Kb + (size_t)r * 32 * HDq;
        const __half* Vt = Vb + (size_t)r * 32 * HDq;

        // ---- scores S = Q @ K^T (32x32), fragments [mt][nt] ----
        float sf[2][4][4];
        #pragma unroll
        for (int mt = 0; mt < 2; mt++)
            #pragma unroll
            for (int nt = 0; nt < 4; nt++)
                #pragma unroll
                for (int j = 0; j < 4; j++) sf[mt][nt][j] = 0.f;

        #pragma unroll
        for (int ks = 0; ks < 4; ks++) {
            uint32_t aq[2][4];
            #pragma unroll
            for (int mt = 0; mt < 2; mt++) {
                const __half* qrow = qs + (16 * mt + gr) * 72 + 16 * ks + 2 * gc;
                aq[mt][0] = *(const uint32_t*)qrow;
                aq[mt][1] = *(const uint32_t*)(qrow + 8 * 72);
                aq[mt][2] = *(const uint32_t*)(qrow + 8);
                aq[mt][3] = *(const uint32_t*)(qrow + 8 * 72 + 8);
            }
            #pragma unroll
            for (int nt = 0; nt < 4; nt++) {
                uint32_t bk[2];
                const __half* kr = Kt + (8 * nt + gr) * HDq + 16 * ks + 2 * gc;
                bk[0] = *(const uint32_t*)kr;
                bk[1] = *(const uint32_t*)(kr + 8);
                mma_f16(sf[0][nt], aq[0], bk);
                mma_f16(sf[1][nt], aq[1], bk);
            }
        }
        #pragma unroll
        for (int mt = 0; mt < 2; mt++)
            #pragma unroll
            for (int nt = 0; nt < 4; nt++)
                #pragma unroll
                for (int j = 0; j < 4; j++) sf[mt][nt][j] *= 0.125f;

        // ---- masked row max ----
        float rmax[4] = {-1e30f, -1e30f, -1e30f, -1e30f};
        #pragma unroll
        for (int mt = 0; mt < 2; mt++)
            #pragma unroll
            for (int hf = 0; hf < 2; hf++) {
                if ((rowbits[2 * mt + hf] >> r) & 1u) {
                    float v = rmax[2 * mt + hf];
                    #pragma unroll
                    for (int nt = 0; nt < 4; nt++) {
                        v = fmaxf(v, sf[mt][nt][2 * hf]);
                        v = fmaxf(v, sf[mt][nt][2 * hf + 1]);
                    }
                    rmax[2 * mt + hf] = v;
                }
            }
        #pragma unroll
        for (int i = 0; i < 4; i++) {
            rmax[i] = fmaxf(rmax[i], __shfl_xor_sync(0xffffffffu, rmax[i], 1));
            rmax[i] = fmaxf(rmax[i], __shfl_xor_sync(0xffffffffu, rmax[i], 2));
        }

        float mnew[4], scl[4];
        #pragma unroll
        for (int i = 0; i < 4; i++) {
            mnew[i] = fmaxf(m4[i], rmax[i]);
            scl[i] = __expf(m4[i] - mnew[i]);   // finite sentinel -1e30 -> underflow to 0
        }

        // ---- p = exp(s - mnew), rounded to fp16 for consistency; row sums ----
        float rsum[4] = {0.f, 0.f, 0.f, 0.f};
        #pragma unroll
        for (int mt = 0; mt < 2; mt++)
            #pragma unroll
            for (int hf = 0; hf < 2; hf++) {
                bool ok = (rowbits[2 * mt + hf] >> r) & 1u;
                #pragma unroll
                for (int nt = 0; nt < 4; nt++)
                    #pragma unroll
                    for (int j2 = 0; j2 < 2; j2++) {
                        int j = 2 * hf + j2;
                        float p = ok ? __expf(sf[mt][nt][j] - mnew[2 * mt + hf]) : 0.f;
                        p = __half2float(__float2half_rn(p));
                        sf[mt][nt][j] = p;
                        rsum[2 * mt + hf] += p;
                    }
            }
        #pragma unroll
        for (int i = 0; i < 4; i++) {
            rsum[i] += __shfl_xor_sync(0xffffffffu, rsum[i], 1);
            rsum[i] += __shfl_xor_sync(0xffffffffu, rsum[i], 2);
            l4[i] = l4[i] * scl[i] + rsum[i];
            m4[i] = mnew[i];
        }

        // ---- rescale acc ----
        #pragma unroll
        for (int mt = 0; mt < 2; mt++)
            #pragma unroll
            for (int nt = 0; nt < 8; nt++) {
                acc[mt][nt][0] *= scl[2 * mt];
                acc[mt][nt][1] *= scl[2 * mt];
                acc[mt][nt][2] *= scl[2 * mt + 1];
                acc[mt][nt][3] *= scl[2 * mt + 1];
            }

        // ---- ctx += P @ V (P from score frags via register conversion) ----
        #pragma unroll
        for (int ks2 = 0; ks2 < 2; ks2++) {
            uint32_t ap[2][4];
            #pragma unroll
            for (int mt = 0; mt < 2; mt++) {
                __half2 t0 = __floats2half2_rn(sf[mt][2 * ks2][0], sf[mt][2 * ks2][1]);
                __half2 t1 = __floats2half2_rn(sf[mt][2 * ks2][2], sf[mt][2 * ks2][3]);
                __half2 t2 = __floats2half2_rn(sf[mt][2 * ks2 + 1][0], sf[mt][2 * ks2 + 1][1]);
                __half2 t3 = __floats2half2_rn(sf[mt][2 * ks2 + 1][2], sf[mt][2 * ks2 + 1][3]);
                ap[mt][0] = *(uint32_t*)&t0;
                ap[mt][1] = *(uint32_t*)&t1;
                ap[mt][2] = *(uint32_t*)&t2;
                ap[mt][3] = *(uint32_t*)&t3;
            }
            #pragma unroll
            for (int nt = 0; nt < 8; nt++) {
                int col = 8 * nt + gr;
                __half v00 = Vt[(16 * ks2 + 2 * gc) * HDq + col];
                __half v01 = Vt[(16 * ks2 + 2 * gc + 1) * HDq + col];
                __half v10 = Vt[(16 * ks2 + 2 * gc + 8) * HDq + col];
                __half v11 = Vt[(16 * ks2 + 2 * gc + 9) * HDq + col];
                __half2 b0 = __halves2half2(v00, v01);
                __half2 b1 = __halves2half2(v10, v11);
                uint32_t bv[2] = { *(uint32_t*)&b0, *(uint32_t*)&b1 };
                mma_f16(acc[0][nt], ap[0], bv);
                mma_f16(acc[1][nt], ap[1], bv);
            }
        }
    }

    // ---- write per-warp state to smem ----
    if (gc == 0) {
        #pragma unroll
        for (int i = 0; i < 4; i++) {
            int row = 16 * (i >> 1) + 8 * (i & 1) + gr;
            ws_m[warp][row] = m4[i];
            ws_l[warp][row] = l4[i];
        }
    }
    #pragma unroll
    for (int mt = 0; mt < 2; mt++)
        #pragma unroll
        for (int nt = 0; nt < 8; nt++) {
            int row = 16 * mt + gr, col = 8 * nt + 2 * gc;
            __half2 h01 = __floats2half2_rn(acc[mt][nt][0], acc[mt][nt][1]);
            __half2 h23 = __floats2half2_rn(acc[mt][nt][2], acc[mt][nt][3]);
            *(__half2*)&acc_s[warp][row][col] = h01;
            *(__half2*)&acc_s[warp][row + 8][col] = h23;
        }
    __syncthreads();

    // ---- merge 8 warps (log-sum-exp) ----
    {
        int row = tid >> 3, dbase = (tid & 7) * 8;
        float M = -1e30f;
        #pragma unroll
        for (int w = 0; w < 8; w++) M = fmaxf(M, ws_m[w][row]);
        float L = 0.f;
        float o[8] = {0.f, 0.f, 0.f, 0.f, 0.f, 0.f, 0.f, 0.f};
        #pragma unroll
        for (int w = 0; w < 8; w++) {
            float wg = __expf(ws_m[w][row] - M);
            L += ws_l[w][row] * wg;
            if (wg != 0.f) {
                #pragma unroll
                for (int d2 = 0; d2 < 4; d2++) {
                    __half2 hv = *(__half2*)&acc_s[w][row][dbase + 2 * d2];
                    float2 f = __half22float2(hv);
                    o[2 * d2]     += f.x * wg;
                    o[2 * d2 + 1] += f.y * wg;
                }
            }
        }
        float inv = 1.f / L;
        __half ob[8];
        #pragma unroll
        for (int d = 0; d < 8; d++) ob[d] = __float2half_rn(o[d] * inv);
        *(uint4*)(ctx + ((size_t)(b * Sq + s0 + row)) * Dq + h * HDq + dbase) = *(uint4*)ob;
    }
}

// ---------------- host launch ----------------
extern "C" void kernel_launch(void* const* d_in, const int* in_sizes, int n_in,
                              void* d_out, int out_size) {
    const float* x      = (const float*)d_in[0];
    const float* Wu     = (const float*)d_in[1];
    const float* Wk_sel = (const float*)d_in[2];
    const float* Wq_sel = (const float*)d_in[3];
    const float* Wq     = (const float*)d_in[4];
    const float* Wk     = (const float*)d_in[5];
    const float* Wv     = (const float*)d_in[6];
    const float* Wo     = (const float*)d_in[7];
    float* out = (float*)d_out;

    float *WuT, *WkselT, *part;
    float *pooled, *root, *ksel, *qsel;
    __half *xh, *Wcat_h, *WoT_h, *ctx_h, *q, *k, *v;
    unsigned char* mask;
    cudaGetSymbolAddress((void**)&xh,      g_xh);
    cudaGetSymbolAddress((void**)&WuT,     g_WuT);
    cudaGetSymbolAddress((void**)&WkselT,  g_WkselT);
    cudaGetSymbolAddress((void**)&Wcat_h,  g_Wcat_h);
    cudaGetSymbolAddress((void**)&WoT_h,   g_WoT_h);
    cudaGetSymbolAddress((void**)&part,    g_part);
    cudaGetSymbolAddress((void**)&pooled,  g_pooled);
    cudaGetSymbolAddress((void**)&root,    g_root);
    cudaGetSymbolAddress((void**)&ksel,    g_ksel);
    cudaGetSymbolAddress((void**)&qsel,    g_qsel);
    cudaGetSymbolAddress((void**)&mask,    g_mask);
    cudaGetSymbolAddress((void**)&q,       g_q);
    cudaGetSymbolAddress((void**)&k,       g_k);
    cudaGetSymbolAddress((void**)&v,       g_v);
    cudaGetSymbolAddress((void**)&ctx_h,   g_ctx_h);

    cudaFuncSetAttribute(mma_gemm_h, cudaFuncAttributeMaxDynamicSharedMemorySize, SM_GEMM_BYTES);

    // (1) x -> xh (fp16)
    round_copy_kernel<<<(Mtok * Dq / 4 + 255) / 256, 256>>>(
        (const float4*)x, (__half2*)xh, Mtok * Dq / 4);
    // (2) all weight transposes
    transpose_all_kernel<<<5632, dim3(32, 8)>>>(Wq_sel, Wq, Wk, Wv, Wu, Wo, Wk_sel,
                                                Wcat_h, WuT, WoT_h, WkselT);
    // (3) pooling
    pool_kernel<<<Bq * Rq, 256>>>(x, pooled);
    // (4) fused fp16: [qsel | q | k | v] = xh @ Wcat^T (q/k/v stored fp16)
    mma_gemm_h<<<dim3(NCAT / GBN, Mtok / GBM), 256, SM_GEMM_BYTES>>>(
        xh, Wcat_h, qsel, Mtok, NCAT, Dq, 4, nullptr, q, k, v);
    // (5-6) root = pooled @ Wu (tf32 split-K + rounded reduce)
    mma_gemm_sk<<<dim3(Dq / 64, (Bq * Rq) / 64, 4), 128>>>(pooled, WuT, part, Bq * Rq, Dq, Dq);
    reduce4_kernel<<<(Bq * Rq * Dq / 4 + 255) / 256, 256>>>((const float4*)part, (float4*)root,
                                                            Bq * Rq * Dq / 4, 1);
    // (7-8) ksel = root @ Wk_sel (tf32 split-K + reduce)
    mma_gemm_sk<<<dim3(DAq / 64, (Bq * Rq) / 64, 4), 128>>>(root, WkselT, part, Bq * Rq, DAq, Dq);
    reduce4_kernel<<<(Bq * Rq * DAq / 4 + 255) / 256, 256>>>((const float4*)part, (float4*)ksel,
                                                             Bq * Rq * DAq / 4, 0);
    // (9) selection mask
    select_kernel<<<dim3(Bq, Sq / 8), 256>>>(qsel, ksel, mask);
    // (10) tensor-core attention (fp16 q/k/v, ctx fp16)
    attn_mma_kernel<<<dim3(Bq * Hq, Sq / 32), 256>>>(q, k, v, mask, ctx_h);
    // (11) out = ctx_h @ Wo^T + x (fp16 GEMM, fp32 residual)
    mma_gemm_h<<<dim3(Dq / GBN, Mtok / GBM), 256, SM_GEMM_BYTES>>>(
        ctx_h, WoT_h, out, Mtok, Dq, Dq, 2, x, nullptr, nullptr, nullptr);
}

// round 15
// speedup vs baseline: 1.2180x; 1.2180x over previous
#include <cuda_runtime.h>
#include <cuda_fp16.h>
#include <math.h>
#include <stdint.h>

// ---------------- problem constants ----------------
#define Bq 8
#define Sq 1024
#define Dq 1024
#define DAq 256
#define Hq 16
#define HDq 64
#define Rq 32
#define Mtok (Bq*Sq)   // 8192
#define NCAT (DAq + 3*Dq)   // 3328

// ---------------- scratch (device globals; no allocation) ----------------
__device__ __half g_xh[Mtok*Dq];                  // fp16 x
__device__ float g_WuT [Dq*Dq];
__device__ float g_WkselT[DAq*Dq];
__device__ __half g_Wcat_h[NCAT*Dq];              // [qsel|q|k|v] transposed fp16
__device__ __half g_WoT_h[Dq*Dq];
__device__ float g_pooled[Bq*Rq*Dq];
__device__ float g_root  [Bq*Rq*Dq];
__device__ float g_ksel  [Bq*Rq*DAq];
__device__ float g_part[4*256*1024];
__device__ float g_qsel  [Mtok*DAq];
__device__ unsigned char g_mask[Mtok*Rq];
__device__ __half g_q [Mtok*Dq];                  // [B,H,S,64] fp16
__device__ __half g_k [Mtok*Dq];
__device__ __half g_v [Mtok*Dq];
__device__ __half g_ctx_h[Mtok*Dq];               // [B,S,D] fp16

// ---------------- helpers ----------------
__device__ __forceinline__ float rna_tf32(float x) {
    uint32_t r; asm("cvt.rna.tf32.f32 %0, %1;" : "=r"(r) : "f"(x));
    return __uint_as_float(r);
}
__device__ __forceinline__ float warp_max(float v) {
    #pragma unroll
    for (int o = 16; o; o >>= 1) v = fmaxf(v, __shfl_xor_sync(0xffffffffu, v, o));
    return v;
}
__device__ __forceinline__ float warp_sum(float v) {
    #pragma unroll
    for (int o = 16; o; o >>= 1) v += __shfl_xor_sync(0xffffffffu, v, o);
    return v;
}
__device__ __forceinline__ uint32_t smem_u32(const void* p) {
    uint32_t a;
    asm("{ .reg .u64 t; cvta.to.shared.u64 t, %1; cvt.u32.u64 %0, t; }" : "=r"(a) : "l"(p));
    return a;
}

#define CP16(dst, src) \
    asm volatile("cp.async.cg.shared.global [%0], [%1], 16;" :: "r"(dst), "l"(src))
#define CPCOMMIT() asm volatile("cp.async.commit_group;")
#define CPWAIT(n)  asm volatile("cp.async.wait_group %0;" :: "n"(n))

#define LDSM4(r0, r1, r2, r3, addr) \
    asm volatile("ldmatrix.sync.aligned.m8n8.x4.shared.b16 {%0,%1,%2,%3}, [%4];" \
        : "=r"(r0), "=r"(r1), "=r"(r2), "=r"(r3) : "r"(addr))

__device__ __forceinline__ void mma_tf32(float c[4], const uint32_t a[4], const uint32_t b[2]) {
    asm volatile(
        "mma.sync.aligned.m16n8k8.row.col.f32.tf32.tf32.f32 "
        "{%0,%1,%2,%3}, {%4,%5,%6,%7}, {%8,%9}, {%0,%1,%2,%3};"
        : "+f"(c[0]), "+f"(c[1]), "+f"(c[2]), "+f"(c[3])
        : "r"(a[0]), "r"(a[1]), "r"(a[2]), "r"(a[3]), "r"(b[0]), "r"(b[1]));
}
__device__ __forceinline__ void mma_f16(float c[4], const uint32_t a[4], const uint32_t b[2]) {
    asm volatile(
        "mma.sync.aligned.m16n8k16.row.col.f32.f16.f16.f32 "
        "{%0,%1,%2,%3}, {%4,%5,%6,%7}, {%8,%9}, {%0,%1,%2,%3};"
        : "+f"(c[0]), "+f"(c[1]), "+f"(c[2]), "+f"(c[3])
        : "r"(a[0]), "r"(a[1]), "r"(a[2]), "r"(a[3]), "r"(b[0]), "r"(b[1]));
}

// ---------------- prep kernels ----------------
__global__ void round_copy_kernel(const float4* __restrict__ in, __half2* __restrict__ xh, int n4) {
    int i = blockIdx.x * blockDim.x + threadIdx.x;
    if (i < n4) {
        float4 v = in[i];
        xh[2 * i]     = __floats2half2_rn(v.x, v.y);
        xh[2 * i + 1] = __floats2half2_rn(v.z, v.w);
    }
}

__global__ void transpose_all_kernel(
    const float* __restrict__ Wq_sel, const float* __restrict__ Wq,
    const float* __restrict__ Wk, const float* __restrict__ Wv,
    const float* __restrict__ Wu, const float* __restrict__ Wo,
    const float* __restrict__ Wk_sel,
    __half* __restrict__ Wcat_h, float* __restrict__ WuT,
    __half* __restrict__ WoT_h, float* __restrict__ WkselT)
{
    __shared__ float t[32][33];
    int tix = blockIdx.x;
    const float* W; int Ndim, seg;
    if (tix < 256)       { seg = 0; W = Wq_sel; Ndim = DAq; }
    else if (tix < 1280) { seg = 1; tix -= 256;  W = Wq; Ndim = Dq; }
    else if (tix < 2304) { seg = 2; tix -= 1280; W = Wk; Ndim = Dq; }
    else if (tix < 3328) { seg = 3; tix -= 2304; W = Wv; Ndim = Dq; }
    else if (tix < 4352) { seg = 4; tix -= 3328; W = Wu; Ndim = Dq; }
    else if (tix < 5376) { seg = 5; tix -= 4352; W = Wo; Ndim = Dq; }
    else                 { seg = 6; tix -= 5376; W = Wk_sel; Ndim = DAq; }
    int ntile = Ndim >> 5;
    int n0 = (tix % ntile) * 32, k0 = (tix / ntile) * 32;
    int tx = threadIdx.x, ty = threadIdx.y;
    #pragma unroll
    for (int i = 0; i < 32; i += 8)
        t[ty + i][tx] = W[(size_t)(k0 + ty + i) * Ndim + n0 + tx];
    __syncthreads();
    if (seg <= 3) {
        size_t base = (seg == 0) ? 0 : (size_t)(DAq + (seg - 1) * Dq) * Dq;
        __half* dst = Wcat_h + base;
        #pragma unroll
        for (int i = 0; i < 32; i += 8)
            dst[(size_t)(n0 + ty + i) * Dq + k0 + tx] = __float2half_rn(t[tx][ty + i]);
    } else if (seg == 5) {
        #pragma unroll
        for (int i = 0; i < 32; i += 8)
            WoT_h[(size_t)(n0 + ty + i) * Dq + k0 + tx] = __float2half_rn(t[tx][ty + i]);
    } else {
        float* dst = (seg == 4) ? WuT : WkselT;
        #pragma unroll
        for (int i = 0; i < 32; i += 8)
            dst[(size_t)(n0 + ty + i) * Dq + k0 + tx] = rna_tf32(t[tx][ty + i]);
    }
}

__global__ void pool_kernel(const float* __restrict__ x, float* __restrict__ pooled) {
    int br = blockIdx.x;
    const float* base = x + (size_t)br * 32 * Dq;
    int d4 = threadIdx.x;
    float4 acc = make_float4(0.f, 0.f, 0.f, 0.f);
    #pragma unroll 4
    for (int i = 0; i < 32; i++) {
        float4 v = *(const float4*)(base + (size_t)i * Dq + d4 * 4);
        acc.x += v.x; acc.y += v.y; acc.z += v.z; acc.w += v.w;
    }
    const float s = 1.0f / 32.0f;
    acc.x = rna_tf32(acc.x * s); acc.y = rna_tf32(acc.y * s);
    acc.z = rna_tf32(acc.z * s); acc.w = rna_tf32(acc.w * s);
    *(float4*)(pooled + (size_t)br * Dq + d4 * 4) = acc;
}

// ---------------- fp16 mma.sync GEMM: 128x128, 256 thr, GBK=64 ----------------
#define GBM 128
#define GBN 128
#define GBK 32
#define GBKB 64
#define ROWB 144
#define OP_H_BYTES (128 * ROWB)
#define STAGE_H_BYTES (2 * OP_H_BYTES)
#define SM_GEMM_BYTES (2 * STAGE_H_BYTES) // 73728

__global__ __launch_bounds__(256, 2)
void mma_gemm_h(const __half* __restrict__ A, const __half* __restrict__ Bt,
                float* __restrict__ C, int M, int N, int Kd,
                int mode, const float* __restrict__ resid,
                __half* __restrict__ pq, __half* __restrict__ pk, __half* __restrict__ pv)
{
    extern __shared__ float smf[];
    int tid = threadIdx.x;
    int wid = tid >> 5, lane = tid & 31;
    int warp_row = wid & 1;
    int warp_col = wid >> 1;
    int gr = lane >> 2, gc = lane & 3;
    int bm = blockIdx.y * GBM;
    int bn = blockIdx.x * GBN;

    int sel = lane >> 3, l8 = lane & 7;
    int a_row_off = (sel & 1) * 8 + l8;
    int a_col16 = (sel >> 1) * 16;
    int b_row_off = (sel >> 1) * 8 + l8;
    int b_col16 = (sel & 1) * 16;

    float c[4][4][4];
    #pragma unroll
    for (int f = 0; f < 4; f++)
        #pragma unroll
        for (int g = 0; g < 4; g++)
            #pragma unroll
            for (int i = 0; i < 4; i++) c[f][g][i] = 0.f;

    uint32_t sbase = smem_u32(smf);
    const int NK = Kd / GBKB;

    auto load_stage = [&](int p, int k0) {
        uint32_t Abase = sbase + (uint32_t)(p * STAGE_H_BYTES);
        uint32_t Bbase = Abase + OP_H_BYTES;
        #pragma unroll
        for (int j = 0; j < 4; j++) {
            int idx = tid + j * 256;
            int row = idx >> 3, kc = idx & 7;
            CP16(Abase + (uint32_t)(row * ROWB + kc * 16),
                 A + (size_t)(bm + row) * Kd + k0 + kc * 8);
        }
        #pragma unroll
        for (int j = 0; j < 4; j++) {
            int idx = tid + j * 256;
            int row = idx >> 3, kc = idx & 7;
            CP16(Bbase + (uint32_t)(row * ROWB + kc * 16),
                 Bt + (size_t)(bn + row) * Kd + k0 + kc * 8);
        }
    };

    load_stage(0, 0);
    CPCOMMIT();

    for (int ks = 0; ks < NK; ks++) {
        int p = ks & 1;
        if (ks + 1 < NK) {
            load_stage(p ^ 1, (ks + 1) * GBKB);
            CPCOMMIT();
            CPWAIT(1);
        } else {
            CPWAIT(0);
        }
        __syncthreads();

        uint32_t As = sbase + (uint32_t)(p * STAGE_H_BYTES);
        uint32_t Bs = As + OP_H_BYTES;
        uint32_t aAddr = As + (uint32_t)((warp_row * 64 + a_row_off) * ROWB + a_col16);
        uint32_t bAddr = Bs + (uint32_t)((warp_col * 32 + b_row_off) * ROWB + b_col16);

        #pragma unroll
        for (int kk = 0; kk < 4; kk++) {
            uint32_t a[4][4], b[4][2];
            #pragma unroll
            for (int f = 0; f < 4; f++)
                LDSM4(a[f][0], a[f][1], a[f][2], a[f][3],
                      aAddr + (uint32_t)(f * 16 * ROWB + kk * 32));
            #pragma unroll
            for (int gp = 0; gp < 2; gp++)
                LDSM4(b[2*gp][0], b[2*gp][1], b[2*gp+1][0], b[2*gp+1][1],
                      bAddr + (uint32_t)(gp * 16 * ROWB + kk * 32));
            #pragma unroll
            for (int f = 0; f < 4; f++)
                #pragma unroll
                for (int g = 0; g < 4; g++)
                    mma_f16(c[f][g], a[f], b[g]);
        }
        __syncthreads();
    }

    float* stg = smf;
    #pragma unroll
    for (int f = 0; f < 4; f++)
        #pragma unroll
        for (int g = 0; g < 4; g++) {
            int r0 = warp_row * 64 + f * 16 + gr;
            int c0 = warp_col * 32 + g * 8 + 2 * gc;
            stg[r0 * 132 + c0]           = c[f][g][0];
            stg[r0 * 132 + c0 + 1]       = c[f][g][1];
            stg[(r0 + 8) * 132 + c0]     = c[f][g][2];
            stg[(r0 + 8) * 132 + c0 + 1] = c[f][g][3];
        }
    __syncthreads();

    int ccol = (tid & 31) * 4;
    #pragma unroll 4
    for (int rr = 0; rr < 16; rr++) {
        int r = (tid >> 5) + rr * 8;
        float4 v;
        v.x = stg[r * 132 + ccol + 0];
        v.y = stg[r * 132 + ccol + 1];
        v.z = stg[r * 132 + ccol + 2];
        v.w = stg[r * 132 + ccol + 3];
        int m = bm + r;
        int n = bn + ccol;
        if (mode == 2) {
            float4 rv = *(const float4*)(resid + (size_t)m * N + n);
            v.x += rv.x; v.y += rv.y; v.z += rv.z; v.w += rv.w;
            *(float4*)(C + (size_t)m * N + n) = v;
        } else {
            if (n < DAq) {
                *(float4*)(C + (size_t)m * DAq + n) = v;
            } else {
                int n2 = n - DAq;
                int proj = n2 >> 10, nn = n2 & 1023;
                int h = nn >> 6, hd = nn & 63;
                int b = m >> 10, s = m & 1023;
                __half* P = (proj == 0) ? pq : (proj == 1) ? pk : pv;
                __half2 h01 = __floats2half2_rn(v.x, v.y);
                __half2 h23 = __floats2half2_rn(v.z, v.w);
                uint2 u = make_uint2(*(uint32_t*)&h01, *(uint32_t*)&h23);
                *(uint2*)(P + (((size_t)(b * Hq + h)) * Sq + s) * HDq + hd) = u;
            }
        }
    }
}

// ---------------- split-K small GEMM (tf32, unchanged) ----------------
#define SKLDT 36
#define SK_STAGE (128 * SKLDT)

__global__ __launch_bounds__(128)
void mma_gemm_sk(const float* __restrict__ A, const float* __restrict__ Bt,
                 float* __restrict__ Cpart, int M, int N, int Kd)
{
    __shared__ float smf[2 * SK_STAGE];
    int tid = threadIdx.x;
    int wid = tid >> 5, lane = tid & 31;
    int warp_row = wid & 1;
    int warp_col = wid >> 1;
    int gr = lane >> 2, gc = lane & 3;
    int bm = blockIdx.y * 64;
    int bn = blockIdx.x * 64;
    int kslice = Kd >> 2;
    int kbase = blockIdx.z * kslice;

    int sel = lane >> 3, l8 = lane & 7;
    int a_row_off = (sel & 1) * 8 + l8;
    int a_col_off = (sel >> 1) * 4;
    int b_row_off = (sel >> 1) * 8 + l8;
    int b_col_off = (sel & 1) * 4;

    float c[2][4][4];
    #pragma unroll
    for (int f = 0; f < 2; f++)
        #pragma unroll
        for (int g = 0; g < 4; g++)
            #pragma unroll
            for (int i = 0; i < 4; i++) c[f][g][i] = 0.f;

    uint32_t sbase = smem_u32(smf);
    const int NK = kslice / GBK;

    auto load_stage = [&](int p, int k0) {
        uint32_t Abase = sbase + (uint32_t)(p * SK_STAGE) * 4;
        uint32_t Bbase = Abase + (uint32_t)(64 * SKLDT) * 4;
        #pragma unroll
        for (int j = 0; j < 4; j++) {
            int idx = tid + j * 128;
            int row = idx >> 3, kc = idx & 7;
            CP16(Abase + (uint32_t)(row * SKLDT + kc * 4) * 4,
                 A + (size_t)(bm + row) * Kd + k0 + kc * 4);
        }
        #pragma unroll
        for (int j = 0; j < 4; j++) {
            int idx = tid + j * 128;
            int row = idx >> 3, kc = idx & 7;
            CP16(Bbase + (uint32_t)(row * SKLDT + kc * 4) * 4,
                 Bt + (size_t)(bn + row) * Kd + k0 + kc * 4);
        }
    };

    load_stage(0, kbase);
    CPCOMMIT();

    for (int ks = 0; ks < NK; ks++) {
        int p = ks & 1;
        if (ks + 1 < NK) {
            load_stage(p ^ 1, kbase + (ks + 1) * GBK);
            CPCOMMIT();
            CPWAIT(1);
        } else {
            CPWAIT(0);
        }
        __syncthreads();

        uint32_t As = sbase + (uint32_t)(p * SK_STAGE) * 4;
        uint32_t Bs = As + (uint32_t)(64 * SKLDT) * 4;
        uint32_t aAddr = As + (uint32_t)((warp_row * 32 + a_row_off) * SKLDT + a_col_off) * 4;
        uint32_t bAddr = Bs + (uint32_t)((warp_col * 32 + b_row_off) * SKLDT + b_col_off) * 4;

        #pragma unroll
        for (int kk = 0; kk < 4; kk++) {
            uint32_t a[2][4], b[4][2];
            #pragma unroll
            for (int f = 0; f < 2; f++)
                LDSM4(a[f][0], a[f][1], a[f][2], a[f][3],
                      aAddr + (uint32_t)(f * 16 * SKLDT + kk * 8) * 4);
            #pragma unroll
            for (int gp = 0; gp < 2; gp++)
                LDSM4(b[2*gp][0], b[2*gp][1], b[2*gp+1][0], b[2*gp+1][1],
                      bAddr + (uint32_t)(gp * 16 * SKLDT + kk * 8) * 4);
            #pragma unroll
            for (int f = 0; f < 2; f++)
                #pragma unroll
                for (int g = 0; g < 4; g++)
                    mma_tf32(c[f][g], a[f], b[g]);
        }
        __syncthreads();
    }

    float* Cp = Cpart + (size_t)blockIdx.z * M * N;
    #pragma unroll
    for (int f = 0; f < 2; f++)
        #pragma unroll
        for (int g = 0; g < 4; g++) {
            int r0 = bm + warp_row * 32 + f * 16 + gr;
            int c0 = bn + warp_col * 32 + g * 8 + 2 * gc;
            *(float2*)(Cp + (size_t)r0 * N + c0)       = make_float2(c[f][g][0], c[f][g][1]);
            *(float2*)(Cp + (size_t)(r0 + 8) * N + c0) = make_float2(c[f][g][2], c[f][g][3]);
        }
}

__global__ void reduce4_kernel(const float4* __restrict__ part, float4* __restrict__ dst,
                               int n4, int do_round) {
    int i = blockIdx.x * blockDim.x + threadIdx.x;
    if (i >= n4) return;
    float4 a = part[i], b = part[i + n4], cc = part[i + 2 * n4], d = part[i + 3 * n4];
    float4 v = make_float4(a.x + b.x + cc.x + d.x, a.y + b.y + cc.y + d.y,
                           a.z + b.z + cc.z + d.z, a.w + b.w + cc.w + d.w);
    if (do_round) {
        v.x = rna_tf32(v.x); v.y = rna_tf32(v.y); v.z = rna_tf32(v.z); v.w = rna_tf32(v.w);
    }
    dst[i] = v;
}

// ---------------- block selection ----------------
__global__ __launch_bounds__(256) void select_kernel(
    const float* __restrict__ qsel, const float* __restrict__ ksel,
    unsigned char* __restrict__ mask)
{
    __shared__ float ks[Rq][DAq + 1];
    __shared__ float qrow[8][DAq];
    int b = blockIdx.x;
    int s0 = blockIdx.y * 8;
    int warp = threadIdx.x >> 5, lane = threadIdx.x & 31;
    int s = s0 + warp;

    const float* kp = ksel + (size_t)b * Rq * DAq;
    for (int i = threadIdx.x; i < Rq * DAq; i += 256)
        ks[i >> 8][i & 255] = kp[i];
    const float* qp = qsel + ((size_t)b * Sq + s) * DAq;
    for (int d = lane; d < DAq; d += 32) qrow[warp][d] = qp[d];
    __syncthreads();

    float logit = 0.f;
    #pragma unroll 8
    for (int d = 0; d < DAq; d++)
        logit += qrow[warp][d] * ks[lane][d];
    logit *= 0.0625f;

    float mx = warp_max(logit);
    float e = expf(logit - mx);
    float sum = warp_sum(e);
    float prob = e / sum;
    bool own = (s >> 5) == lane;
    mask[((size_t)b * Sq + s) * Rq + lane] = (prob >= 0.5f || own) ? 1 : 0;
}

// ---------------- block-sparse attention (32 q/CTA, register-prefetch tiles) ----------------
__global__ __launch_bounds__(256) void attn_kernel(
    const __half* __restrict__ Q, const __half* __restrict__ K,
    const __half* __restrict__ V, const unsigned char* __restrict__ mask,
    __half* __restrict__ ctx)
{
    __shared__ float qs[32][68];
    __shared__ float kt[32][68];
    __shared__ float vt[32][68];
    __shared__ uint32_t qbits[32];
    __shared__ int blist[32];
    __shared__ int nblk_s;

    int bh = blockIdx.x;
    int b = bh >> 4, h = bh & 15;
    int s0 = blockIdx.y * 32;
    int tid = threadIdx.x, warp = tid >> 5, lane = tid & 31;
    int row = tid >> 3, c8 = (tid & 7) * 8;

    // Q tile fp16 -> fp32 smem
    {
        uint4 raw = *(const uint4*)(Q + ((size_t)bh * Sq + s0 + row) * HDq + c8);
        const __half2* hp = (const __half2*)&raw;
        #pragma unroll
        for (int j = 0; j < 4; j++) {
            float2 f = __half22float2(hp[j]);
            qs[row][c8 + 2 * j] = f.x;
            qs[row][c8 + 2 * j + 1] = f.y;
        }
    }

    if (warp == 0) {
        const unsigned char* mrow = mask + ((size_t)b * Sq + s0 + lane) * Rq;
        uint32_t bits = 0;
        #pragma unroll
        for (int r = 0; r < Rq; r++) bits |= (mrow[r] ? 1u : 0u) << r;
        qbits[lane] = bits;
        uint32_t u = bits;
        #pragma unroll
        for (int o = 16; o; o >>= 1) u |= __shfl_xor_sync(0xffffffffu, u, o);
        if (lane == 0) {
            int n = 0;
            for (int r = 0; r < 32; r++)
                if ((u >> r) & 1u) blist[n++] = r;
            nblk_s = n;
        }
    }
    __syncthreads();
    int nblk = nblk_s;
    uint32_t myb[4];
    #pragma unroll
    for (int j = 0; j < 4; j++) myb[j] = qbits[warp * 4 + j];

    float mr[4], l[4], c0[4], c1[4];
    #pragma unroll
    for (int j = 0; j < 4; j++) { mr[j] = -INFINITY; l[j] = 0.f; c0[j] = 0.f; c1[j] = 0.f; }

    const __half* kbh = K + (size_t)bh * Sq * HDq;
    const __half* vbh = V + (size_t)bh * Sq * HDq;

    // prefetch block 0 into registers
    uint4 rk, rv;
    {
        int r = blist[0];
        rk = *(const uint4*)(kbh + ((size_t)r * 32 + row) * HDq + c8);
        rv = *(const uint4*)(vbh + ((size_t)r * 32 + row) * HDq + c8);
    }

    for (int i = 0; i < nblk; i++) {
        int r = blist[i];
        __syncthreads();   // previous compute done; tiles free
        {
            const __half2* hk = (const __half2*)&rk;
            const __half2* hv = (const __half2*)&rv;
            #pragma unroll
            for (int j = 0; j < 4; j++) {
                float2 fk = __half22float2(hk[j]);
                float2 fv = __half22float2(hv[j]);
                kt[row][c8 + 2 * j] = fk.x; kt[row][c8 + 2 * j + 1] = fk.y;
                vt[row][c8 + 2 * j] = fv.x; vt[row][c8 + 2 * j + 1] = fv.y;
            }
        }
        if (i + 1 < nblk) {
            int rn = blist[i + 1];
            rk = *(const uint4*)(kbh + ((size_t)rn * 32 + row) * HDq + c8);
            rv = *(const uint4*)(vbh + ((size_t)rn * 32 + row) * HDq + c8);
        }
        __syncthreads();   // tiles ready

        #pragma unroll
        for (int j = 0; j < 4; j++) {
            if (!((myb[j] >> r) & 1u)) continue;
            int qi = warp * 4 + j;
            float sc = 0.f;
            #pragma unroll
            for (int d = 0; d < HDq; d += 4) {
                float4 kv = *(const float4*)&kt[lane][d];
                float4 qv = *(const float4*)&qs[qi][d];
                sc += kv.x * qv.x + kv.y * qv.y + kv.z * qv.z + kv.w * qv.w;
            }
            sc *= 0.125f;
            float bmax = warp_max(sc);
            float mnew = fmaxf(mr[j], bmax);
            float p = __expf(sc - mnew);
            float scale = __expf(mr[j] - mnew);
            l[j] = l[j] * scale + warp_sum(p);
            c0[j] *= scale; c1[j] *= scale;
            #pragma unroll 8
            for (int t = 0; t < 32; t++) {
                float pj = __shfl_sync(0xffffffffu, p, t);
                c0[j] += pj * vt[t][lane];
                c1[j] += pj * vt[t][lane + 32];
            }
            mr[j] = mnew;
        }
    }

    #pragma unroll
    for (int j = 0; j < 4; j++) {
        int s = s0 + warp * 4 + j;
        float inv = 1.0f / l[j];
        __half* cp = ctx + ((size_t)(b * Sq + s)) * Dq + h * HDq;
        cp[lane] = __float2half_rn(c0[j] * inv);
        cp[lane + 32] = __float2half_rn(c1[j] * inv);
    }
}

// ---------------- host launch ----------------
extern "C" void kernel_launch(void* const* d_in, const int* in_sizes, int n_in,
                              void* d_out, int out_size) {
    const float* x      = (const float*)d_in[0];
    const float* Wu     = (const float*)d_in[1];
    const float* Wk_sel = (const float*)d_in[2];
    const float* Wq_sel = (const float*)d_in[3];
    const float* Wq     = (const float*)d_in[4];
    const float* Wk     = (const float*)d_in[5];
    const float* Wv     = (const float*)d_in[6];
    const float* Wo     = (const float*)d_in[7];
    float* out = (float*)d_out;

    float *WuT, *WkselT, *part;
    float *pooled, *root, *ksel, *qsel;
    __half *xh, *Wcat_h, *WoT_h, *ctx_h, *q, *k, *v;
    unsigned char* mask;
    cudaGetSymbolAddress((void**)&xh,      g_xh);
    cudaGetSymbolAddress((void**)&WuT,     g_WuT);
    cudaGetSymbolAddress((void**)&WkselT,  g_WkselT);
    cudaGetSymbolAddress((void**)&Wcat_h,  g_Wcat_h);
    cudaGetSymbolAddress((void**)&WoT_h,   g_WoT_h);
    cudaGetSymbolAddress((void**)&part,    g_part);
    cudaGetSymbolAddress((void**)&pooled,  g_pooled);
    cudaGetSymbolAddress((void**)&root,    g_root);
    cudaGetSymbolAddress((void**)&ksel,    g_ksel);
    cudaGetSymbolAddress((void**)&qsel,    g_qsel);
    cudaGetSymbolAddress((void**)&mask,    g_mask);
    cudaGetSymbolAddress((void**)&q,       g_q);
    cudaGetSymbolAddress((void**)&k,       g_k);
    cudaGetSymbolAddress((void**)&v,       g_v);
    cudaGetSymbolAddress((void**)&ctx_h,   g_ctx_h);

    cudaFuncSetAttribute(mma_gemm_h, cudaFuncAttributeMaxDynamicSharedMemorySize, SM_GEMM_BYTES);

    // (1) x -> xh (fp16)
    round_copy_kernel<<<(Mtok * Dq / 4 + 255) / 256, 256>>>(
        (const float4*)x, (__half2*)xh, Mtok * Dq / 4);
    // (2) all weight transposes
    transpose_all_kernel<<<5632, dim3(32, 8)>>>(Wq_sel, Wq, Wk, Wv, Wu, Wo, Wk_sel,
                                                Wcat_h, WuT, WoT_h, WkselT);
    // (3) pooling
    pool_kernel<<<Bq * Rq, 256>>>(x, pooled);
    // (4) fused fp16: [qsel | q | k | v] = xh @ Wcat^T (q/k/v stored fp16)
    mma_gemm_h<<<dim3(NCAT / GBN, Mtok / GBM), 256, SM_GEMM_BYTES>>>(
        xh, Wcat_h, qsel, Mtok, NCAT, Dq, 4, nullptr, q, k, v);
    // (5-6) root = pooled @ Wu (tf32 split-K + rounded reduce)
    mma_gemm_sk<<<dim3(Dq / 64, (Bq * Rq) / 64, 4), 128>>>(pooled, WuT, part, Bq * Rq, Dq, Dq);
    reduce4_kernel<<<(Bq * Rq * Dq / 4 + 255) / 256, 256>>>((const float4*)part, (float4*)root,
                                                            Bq * Rq * Dq / 4, 1);
    // (7-8) ksel = root @ Wk_sel (tf32 split-K + reduce)
    mma_gemm_sk<<<dim3(DAq / 64, (Bq * Rq) / 64, 4), 128>>>(root, WkselT, part, Bq * Rq, DAq, Dq);
    reduce4_kernel<<<(Bq * Rq * DAq / 4 + 255) / 256, 256>>>((const float4*)part, (float4*)ksel,
                                                             Bq * Rq * DAq / 4, 0);
    // (9) selection mask
    select_kernel<<<dim3(Bq, Sq / 8), 256>>>(qsel, ksel, mask);
    // (10) attention (fp16 q/k/v, register-prefetch double buffering)
    attn_kernel<<<dim3(Bq * Hq, Sq / 32), 256>>>(q, k, v, mask, ctx_h);
    // (11) out = ctx_h @ Wo^T + x (fp16 GEMM, fp32 residual)
    mma_gemm_h<<<dim3(Dq / GBN, Mtok / GBM), 256, SM_GEMM_BYTES>>>(
        ctx_h, WoT_h, out, Mtok, Dq, Dq, 2, x, nullptr, nullptr, nullptr);
}

// round 16
// speedup vs baseline: 1.2302x; 1.0100x over previous
#include <cuda_runtime.h>
#include <cuda_fp16.h>
#include <math.h>
#include <stdint.h>

// ---------------- problem constants ----------------
#define Bq 8
#define Sq 1024
#define Dq 1024
#define DAq 256
#define Hq 16
#define HDq 64
#define Rq 32
#define Mtok (Bq*Sq)   // 8192
#define NCAT (DAq + 3*Dq)   // 3328

// ---------------- scratch (device globals; no allocation) ----------------
__device__ __half g_xh[Mtok*Dq];                  // fp16 x
__device__ float g_WuT [Dq*Dq];
__device__ float g_WkselT[DAq*Dq];
__device__ __half g_Wcat_h[NCAT*Dq];              // [qsel|q|k|v] transposed fp16
__device__ __half g_WoT_h[Dq*Dq];
__device__ float g_pooled[Bq*Rq*Dq];
__device__ float g_root  [Bq*Rq*Dq];
__device__ float g_ksel  [Bq*Rq*DAq];
__device__ float g_part[4*256*1024];
__device__ float g_qsel  [Mtok*DAq];
__device__ unsigned char g_mask[Mtok*Rq];
__device__ __half g_q [Mtok*Dq];                  // [B,H,S,64] fp16
__device__ __half g_k [Mtok*Dq];
__device__ __half g_v [Mtok*Dq];
__device__ __half g_ctx_h[Mtok*Dq];               // [B,S,D] fp16

// ---------------- helpers ----------------
__device__ __forceinline__ float rna_tf32(float x) {
    uint32_t r; asm("cvt.rna.tf32.f32 %0, %1;" : "=r"(r) : "f"(x));
    return __uint_as_float(r);
}
__device__ __forceinline__ float warp_max(float v) {
    #pragma unroll
    for (int o = 16; o; o >>= 1) v = fmaxf(v, __shfl_xor_sync(0xffffffffu, v, o));
    return v;
}
__device__ __forceinline__ float warp_sum(float v) {
    #pragma unroll
    for (int o = 16; o; o >>= 1) v += __shfl_xor_sync(0xffffffffu, v, o);
    return v;
}
__device__ __forceinline__ uint32_t smem_u32(const void* p) {
    uint32_t a;
    asm("{ .reg .u64 t; cvta.to.shared.u64 t, %1; cvt.u32.u64 %0, t; }" : "=r"(a) : "l"(p));
    return a;
}
// packed dual-fp32 FMA (sm_100 base ISA, PTX 8.6)
__device__ __forceinline__ uint64_t fma2(uint64_t a, uint64_t b, uint64_t c) {
    asm("fma.rn.f32x2 %0, %1, %2, %3;" : "=l"(c) : "l"(a), "l"(b), "l"(c));
    return c;
}

#define CP16(dst, src) \
    asm volatile("cp.async.cg.shared.global [%0], [%1], 16;" :: "r"(dst), "l"(src))
#define CPCOMMIT() asm volatile("cp.async.commit_group;")
#define CPWAIT(n)  asm volatile("cp.async.wait_group %0;" :: "n"(n))

#define LDSM4(r0, r1, r2, r3, addr) \
    asm volatile("ldmatrix.sync.aligned.m8n8.x4.shared.b16 {%0,%1,%2,%3}, [%4];" \
        : "=r"(r0), "=r"(r1), "=r"(r2), "=r"(r3) : "r"(addr))

__device__ __forceinline__ void mma_tf32(float c[4], const uint32_t a[4], const uint32_t b[2]) {
    asm volatile(
        "mma.sync.aligned.m16n8k8.row.col.f32.tf32.tf32.f32 "
        "{%0,%1,%2,%3}, {%4,%5,%6,%7}, {%8,%9}, {%0,%1,%2,%3};"
        : "+f"(c[0]), "+f"(c[1]), "+f"(c[2]), "+f"(c[3])
        : "r"(a[0]), "r"(a[1]), "r"(a[2]), "r"(a[3]), "r"(b[0]), "r"(b[1]));
}
__device__ __forceinline__ void mma_f16(float c[4], const uint32_t a[4], const uint32_t b[2]) {
    asm volatile(
        "mma.sync.aligned.m16n8k16.row.col.f32.f16.f16.f32 "
        "{%0,%1,%2,%3}, {%4,%5,%6,%7}, {%8,%9}, {%0,%1,%2,%3};"
        : "+f"(c[0]), "+f"(c[1]), "+f"(c[2]), "+f"(c[3])
        : "r"(a[0]), "r"(a[1]), "r"(a[2]), "r"(a[3]), "r"(b[0]), "r"(b[1]));
}

// ---------------- prep kernels ----------------
__global__ void round_copy_kernel(const float4* __restrict__ in, __half2* __restrict__ xh, int n4) {
    int i = blockIdx.x * blockDim.x + threadIdx.x;
    if (i < n4) {
        float4 v = in[i];
        xh[2 * i]     = __floats2half2_rn(v.x, v.y);
        xh[2 * i + 1] = __floats2half2_rn(v.z, v.w);
    }
}

__global__ void transpose_all_kernel(
    const float* __restrict__ Wq_sel, const float* __restrict__ Wq,
    const float* __restrict__ Wk, const float* __restrict__ Wv,
    const float* __restrict__ Wu, const float* __restrict__ Wo,
    const float* __restrict__ Wk_sel,
    __half* __restrict__ Wcat_h, float* __restrict__ WuT,
    __half* __restrict__ WoT_h, float* __restrict__ WkselT)
{
    __shared__ float t[32][33];
    int tix = blockIdx.x;
    const float* W; int Ndim, seg;
    if (tix < 256)       { seg = 0; W = Wq_sel; Ndim = DAq; }
    else if (tix < 1280) { seg = 1; tix -= 256;  W = Wq; Ndim = Dq; }
    else if (tix < 2304) { seg = 2; tix -= 1280; W = Wk; Ndim = Dq; }
    else if (tix < 3328) { seg = 3; tix -= 2304; W = Wv; Ndim = Dq; }
    else if (tix < 4352) { seg = 4; tix -= 3328; W = Wu; Ndim = Dq; }
    else if (tix < 5376) { seg = 5; tix -= 4352; W = Wo; Ndim = Dq; }
    else                 { seg = 6; tix -= 5376; W = Wk_sel; Ndim = DAq; }
    int ntile = Ndim >> 5;
    int n0 = (tix % ntile) * 32, k0 = (tix / ntile) * 32;
    int tx = threadIdx.x, ty = threadIdx.y;
    #pragma unroll
    for (int i = 0; i < 32; i += 8)
        t[ty + i][tx] = W[(size_t)(k0 + ty + i) * Ndim + n0 + tx];
    __syncthreads();
    if (seg <= 3) {
        size_t base = (seg == 0) ? 0 : (size_t)(DAq + (seg - 1) * Dq) * Dq;
        __half* dst = Wcat_h + base;
        #pragma unroll
        for (int i = 0; i < 32; i += 8)
            dst[(size_t)(n0 + ty + i) * Dq + k0 + tx] = __float2half_rn(t[tx][ty + i]);
    } else if (seg == 5) {
        #pragma unroll
        for (int i = 0; i < 32; i += 8)
            WoT_h[(size_t)(n0 + ty + i) * Dq + k0 + tx] = __float2half_rn(t[tx][ty + i]);
    } else {
        float* dst = (seg == 4) ? WuT : WkselT;
        #pragma unroll
        for (int i = 0; i < 32; i += 8)
            dst[(size_t)(n0 + ty + i) * Dq + k0 + tx] = rna_tf32(t[tx][ty + i]);
    }
}

__global__ void pool_kernel(const float* __restrict__ x, float* __restrict__ pooled) {
    int br = blockIdx.x;
    const float* base = x + (size_t)br * 32 * Dq;
    int d4 = threadIdx.x;
    float4 acc = make_float4(0.f, 0.f, 0.f, 0.f);
    #pragma unroll 4
    for (int i = 0; i < 32; i++) {
        float4 v = *(const float4*)(base + (size_t)i * Dq + d4 * 4);
        acc.x += v.x; acc.y += v.y; acc.z += v.z; acc.w += v.w;
    }
    const float s = 1.0f / 32.0f;
    acc.x = rna_tf32(acc.x * s); acc.y = rna_tf32(acc.y * s);
    acc.z = rna_tf32(acc.z * s); acc.w = rna_tf32(acc.w * s);
    *(float4*)(pooled + (size_t)br * Dq + d4 * 4) = acc;
}

// ---------------- fp16 mma.sync GEMM: 128x128, 256 thr, GBK=64 ----------------
#define GBM 128
#define GBN 128
#define GBK 32
#define GBKB 64
#define ROWB 144
#define OP_H_BYTES (128 * ROWB)
#define STAGE_H_BYTES (2 * OP_H_BYTES)
#define SM_GEMM_BYTES (2 * STAGE_H_BYTES) // 73728

__global__ __launch_bounds__(256, 2)
void mma_gemm_h(const __half* __restrict__ A, const __half* __restrict__ Bt,
                float* __restrict__ C, int M, int N, int Kd,
                int mode, const float* __restrict__ resid,
                __half* __restrict__ pq, __half* __restrict__ pk, __half* __restrict__ pv)
{
    extern __shared__ float smf[];
    int tid = threadIdx.x;
    int wid = tid >> 5, lane = tid & 31;
    int warp_row = wid & 1;
    int warp_col = wid >> 1;
    int gr = lane >> 2, gc = lane & 3;
    int bm = blockIdx.y * GBM;
    int bn = blockIdx.x * GBN;

    int sel = lane >> 3, l8 = lane & 7;
    int a_row_off = (sel & 1) * 8 + l8;
    int a_col16 = (sel >> 1) * 16;
    int b_row_off = (sel >> 1) * 8 + l8;
    int b_col16 = (sel & 1) * 16;

    float c[4][4][4];
    #pragma unroll
    for (int f = 0; f < 4; f++)
        #pragma unroll
        for (int g = 0; g < 4; g++)
            #pragma unroll
            for (int i = 0; i < 4; i++) c[f][g][i] = 0.f;

    uint32_t sbase = smem_u32(smf);
    const int NK = Kd / GBKB;

    auto load_stage = [&](int p, int k0) {
        uint32_t Abase = sbase + (uint32_t)(p * STAGE_H_BYTES);
        uint32_t Bbase = Abase + OP_H_BYTES;
        #pragma unroll
        for (int j = 0; j < 4; j++) {
            int idx = tid + j * 256;
            int row = idx >> 3, kc = idx & 7;
            CP16(Abase + (uint32_t)(row * ROWB + kc * 16),
                 A + (size_t)(bm + row) * Kd + k0 + kc * 8);
        }
        #pragma unroll
        for (int j = 0; j < 4; j++) {
            int idx = tid + j * 256;
            int row = idx >> 3, kc = idx & 7;
            CP16(Bbase + (uint32_t)(row * ROWB + kc * 16),
                 Bt + (size_t)(bn + row) * Kd + k0 + kc * 8);
        }
    };

    load_stage(0, 0);
    CPCOMMIT();

    for (int ks = 0; ks < NK; ks++) {
        int p = ks & 1;
        if (ks + 1 < NK) {
            load_stage(p ^ 1, (ks + 1) * GBKB);
            CPCOMMIT();
            CPWAIT(1);
        } else {
            CPWAIT(0);
        }
        __syncthreads();

        uint32_t As = sbase + (uint32_t)(p * STAGE_H_BYTES);
        uint32_t Bs = As + OP_H_BYTES;
        uint32_t aAddr = As + (uint32_t)((warp_row * 64 + a_row_off) * ROWB + a_col16);
        uint32_t bAddr = Bs + (uint32_t)((warp_col * 32 + b_row_off) * ROWB + b_col16);

        #pragma unroll
        for (int kk = 0; kk < 4; kk++) {
            uint32_t a[4][4], b[4][2];
            #pragma unroll
            for (int f = 0; f < 4; f++)
                LDSM4(a[f][0], a[f][1], a[f][2], a[f][3],
                      aAddr + (uint32_t)(f * 16 * ROWB + kk * 32));
            #pragma unroll
            for (int gp = 0; gp < 2; gp++)
                LDSM4(b[2*gp][0], b[2*gp][1], b[2*gp+1][0], b[2*gp+1][1],
                      bAddr + (uint32_t)(gp * 16 * ROWB + kk * 32));
            #pragma unroll
            for (int f = 0; f < 4; f++)
                #pragma unroll
                for (int g = 0; g < 4; g++)
                    mma_f16(c[f][g], a[f], b[g]);
        }
        __syncthreads();
    }

    float* stg = smf;
    #pragma unroll
    for (int f = 0; f < 4; f++)
        #pragma unroll
        for (int g = 0; g < 4; g++) {
            int r0 = warp_row * 64 + f * 16 + gr;
            int c0 = warp_col * 32 + g * 8 + 2 * gc;
            stg[r0 * 132 + c0]           = c[f][g][0];
            stg[r0 * 132 + c0 + 1]       = c[f][g][1];
            stg[(r0 + 8) * 132 + c0]     = c[f][g][2];
            stg[(r0 + 8) * 132 + c0 + 1] = c[f][g][3];
        }
    __syncthreads();

    int ccol = (tid & 31) * 4;
    #pragma unroll 4
    for (int rr = 0; rr < 16; rr++) {
        int r = (tid >> 5) + rr * 8;
        float4 v;
        v.x = stg[r * 132 + ccol + 0];
        v.y = stg[r * 132 + ccol + 1];
        v.z = stg[r * 132 + ccol + 2];
        v.w = stg[r * 132 + ccol + 3];
        int m = bm + r;
        int n = bn + ccol;
        if (mode == 2) {
            float4 rv = *(const float4*)(resid + (size_t)m * N + n);
            v.x += rv.x; v.y += rv.y; v.z += rv.z; v.w += rv.w;
            *(float4*)(C + (size_t)m * N + n) = v;
        } else {
            if (n < DAq) {
                *(float4*)(C + (size_t)m * DAq + n) = v;
            } else {
                int n2 = n - DAq;
                int proj = n2 >> 10, nn = n2 & 1023;
                int h = nn >> 6, hd = nn & 63;
                int b = m >> 10, s = m & 1023;
                __half* P = (proj == 0) ? pq : (proj == 1) ? pk : pv;
                __half2 h01 = __floats2half2_rn(v.x, v.y);
                __half2 h23 = __floats2half2_rn(v.z, v.w);
                uint2 u = make_uint2(*(uint32_t*)&h01, *(uint32_t*)&h23);
                *(uint2*)(P + (((size_t)(b * Hq + h)) * Sq + s) * HDq + hd) = u;
            }
        }
    }
}

// ---------------- split-K small GEMM (tf32, unchanged) ----------------
#define SKLDT 36
#define SK_STAGE (128 * SKLDT)

__global__ __launch_bounds__(128)
void mma_gemm_sk(const float* __restrict__ A, const float* __restrict__ Bt,
                 float* __restrict__ Cpart, int M, int N, int Kd)
{
    __shared__ float smf[2 * SK_STAGE];
    int tid = threadIdx.x;
    int wid = tid >> 5, lane = tid & 31;
    int warp_row = wid & 1;
    int warp_col = wid >> 1;
    int gr = lane >> 2, gc = lane & 3;
    int bm = blockIdx.y * 64;
    int bn = blockIdx.x * 64;
    int kslice = Kd >> 2;
    int kbase = blockIdx.z * kslice;

    int sel = lane >> 3, l8 = lane & 7;
    int a_row_off = (sel & 1) * 8 + l8;
    int a_col_off = (sel >> 1) * 4;
    int b_row_off = (sel >> 1) * 8 + l8;
    int b_col_off = (sel & 1) * 4;

    float c[2][4][4];
    #pragma unroll
    for (int f = 0; f < 2; f++)
        #pragma unroll
        for (int g = 0; g < 4; g++)
            #pragma unroll
            for (int i = 0; i < 4; i++) c[f][g][i] = 0.f;

    uint32_t sbase = smem_u32(smf);
    const int NK = kslice / GBK;

    auto load_stage = [&](int p, int k0) {
        uint32_t Abase = sbase + (uint32_t)(p * SK_STAGE) * 4;
        uint32_t Bbase = Abase + (uint32_t)(64 * SKLDT) * 4;
        #pragma unroll
        for (int j = 0; j < 4; j++) {
            int idx = tid + j * 128;
            int row = idx >> 3, kc = idx & 7;
            CP16(Abase + (uint32_t)(row * SKLDT + kc * 4) * 4,
                 A + (size_t)(bm + row) * Kd + k0 + kc * 4);
        }
        #pragma unroll
        for (int j = 0; j < 4; j++) {
            int idx = tid + j * 128;
            int row = idx >> 3, kc = idx & 7;
            CP16(Bbase + (uint32_t)(row * SKLDT + kc * 4) * 4,
                 Bt + (size_t)(bn + row) * Kd + k0 + kc * 4);
        }
    };

    load_stage(0, kbase);
    CPCOMMIT();

    for (int ks = 0; ks < NK; ks++) {
        int p = ks & 1;
        if (ks + 1 < NK) {
            load_stage(p ^ 1, kbase + (ks + 1) * GBK);
            CPCOMMIT();
            CPWAIT(1);
        } else {
            CPWAIT(0);
        }
        __syncthreads();

        uint32_t As = sbase + (uint32_t)(p * SK_STAGE) * 4;
        uint32_t Bs = As + (uint32_t)(64 * SKLDT) * 4;
        uint32_t aAddr = As + (uint32_t)((warp_row * 32 + a_row_off) * SKLDT + a_col_off) * 4;
        uint32_t bAddr = Bs + (uint32_t)((warp_col * 32 + b_row_off) * SKLDT + b_col_off) * 4;

        #pragma unroll
        for (int kk = 0; kk < 4; kk++) {
            uint32_t a[2][4], b[4][2];
            #pragma unroll
            for (int f = 0; f < 2; f++)
                LDSM4(a[f][0], a[f][1], a[f][2], a[f][3],
                      aAddr + (uint32_t)(f * 16 * SKLDT + kk * 8) * 4);
            #pragma unroll
            for (int gp = 0; gp < 2; gp++)
                LDSM4(b[2*gp][0], b[2*gp][1], b[2*gp+1][0], b[2*gp+1][1],
                      bAddr + (uint32_t)(gp * 16 * SKLDT + kk * 8) * 4);
            #pragma unroll
            for (int f = 0; f < 2; f++)
                #pragma unroll
                for (int g = 0; g < 4; g++)
                    mma_tf32(c[f][g], a[f], b[g]);
        }
        __syncthreads();
    }

    float* Cp = Cpart + (size_t)blockIdx.z * M * N;
    #pragma unroll
    for (int f = 0; f < 2; f++)
        #pragma unroll
        for (int g = 0; g < 4; g++) {
            int r0 = bm + warp_row * 32 + f * 16 + gr;
            int c0 = bn + warp_col * 32 + g * 8 + 2 * gc;
            *(float2*)(Cp + (size_t)r0 * N + c0)       = make_float2(c[f][g][0], c[f][g][1]);
            *(float2*)(Cp + (size_t)(r0 + 8) * N + c0) = make_float2(c[f][g][2], c[f][g][3]);
        }
}

__global__ void reduce4_kernel(const float4* __restrict__ part, float4* __restrict__ dst,
                               int n4, int do_round) {
    int i = blockIdx.x * blockDim.x + threadIdx.x;
    if (i >= n4) return;
    float4 a = part[i], b = part[i + n4], cc = part[i + 2 * n4], d = part[i + 3 * n4];
    float4 v = make_float4(a.x + b.x + cc.x + d.x, a.y + b.y + cc.y + d.y,
                           a.z + b.z + cc.z + d.z, a.w + b.w + cc.w + d.w);
    if (do_round) {
        v.x = rna_tf32(v.x); v.y = rna_tf32(v.y); v.z = rna_tf32(v.z); v.w = rna_tf32(v.w);
    }
    dst[i] = v;
}

// ---------------- block selection ----------------
__global__ __launch_bounds__(256) void select_kernel(
    const float* __restrict__ qsel, const float* __restrict__ ksel,
    unsigned char* __restrict__ mask)
{
    __shared__ float ks[Rq][DAq + 1];
    __shared__ float qrow[8][DAq];
    int b = blockIdx.x;
    int s0 = blockIdx.y * 8;
    int warp = threadIdx.x >> 5, lane = threadIdx.x & 31;
    int s = s0 + warp;

    const float* kp = ksel + (size_t)b * Rq * DAq;
    for (int i = threadIdx.x; i < Rq * DAq; i += 256)
        ks[i >> 8][i & 255] = kp[i];
    const float* qp = qsel + ((size_t)b * Sq + s) * DAq;
    for (int d = lane; d < DAq; d += 32) qrow[warp][d] = qp[d];
    __syncthreads();

    float logit = 0.f;
    #pragma unroll 8
    for (int d = 0; d < DAq; d++)
        logit += qrow[warp][d] * ks[lane][d];
    logit *= 0.0625f;

    float mx = warp_max(logit);
    float e = expf(logit - mx);
    float sum = warp_sum(e);
    float prob = e / sum;
    bool own = (s >> 5) == lane;
    mask[((size_t)b * Sq + s) * Rq + lane] = (prob >= 0.5f || own) ? 1 : 0;
}

// ---------------- block-sparse attention (32 q/CTA, f32x2 packed math) ----------------
__global__ __launch_bounds__(256) void attn_kernel(
    const __half* __restrict__ Q, const __half* __restrict__ K,
    const __half* __restrict__ V, const unsigned char* __restrict__ mask,
    __half* __restrict__ ctx)
{
    __shared__ float qs[32][68];
    __shared__ float kt[32][68];
    __shared__ float2 vt2[32][36];   // vt2[t][lane] = (v[t][lane], v[t][lane+32])
    __shared__ uint32_t qbits[32];
    __shared__ int blist[32];
    __shared__ int nblk_s;

    int bh = blockIdx.x;
    int b = bh >> 4, h = bh & 15;
    int s0 = blockIdx.y * 32;
    int tid = threadIdx.x, warp = tid >> 5, lane = tid & 31;
    int row = tid >> 3, c8 = (tid & 7) * 8, c4 = (tid & 7) * 4;

    // Q tile fp16 -> fp32 smem
    {
        uint4 raw = *(const uint4*)(Q + ((size_t)bh * Sq + s0 + row) * HDq + c8);
        const __half2* hp = (const __half2*)&raw;
        #pragma unroll
        for (int j = 0; j < 4; j++) {
            float2 f = __half22float2(hp[j]);
            qs[row][c8 + 2 * j] = f.x;
            qs[row][c8 + 2 * j + 1] = f.y;
        }
    }

    if (warp == 0) {
        const unsigned char* mrow = mask + ((size_t)b * Sq + s0 + lane) * Rq;
        uint32_t bits = 0;
        #pragma unroll
        for (int r = 0; r < Rq; r++) bits |= (mrow[r] ? 1u : 0u) << r;
        qbits[lane] = bits;
        uint32_t u = bits;
        #pragma unroll
        for (int o = 16; o; o >>= 1) u |= __shfl_xor_sync(0xffffffffu, u, o);
        if (lane == 0) {
            int n = 0;
            for (int r = 0; r < 32; r++)
                if ((u >> r) & 1u) blist[n++] = r;
            nblk_s = n;
        }
    }
    __syncthreads();
    int nblk = nblk_s;
    uint32_t myb[4];
    #pragma unroll
    for (int j = 0; j < 4; j++) myb[j] = qbits[warp * 4 + j];

    float mr[4], l[4];
    float2 cacc[4];
    #pragma unroll
    for (int j = 0; j < 4; j++) { mr[j] = -INFINITY; l[j] = 0.f; cacc[j] = make_float2(0.f, 0.f); }

    const __half* kbh = K + (size_t)bh * Sq * HDq;
    const __half* vbh = V + (size_t)bh * Sq * HDq;

    // prefetch block 0: K 8 cols (uint4), V pair-cols c4 & c4+32 (2x uint2)
    uint4 rk; uint2 rv0, rv1;
    {
        int r = blist[0];
        rk  = *(const uint4*)(kbh + ((size_t)r * 32 + row) * HDq + c8);
        rv0 = *(const uint2*)(vbh + ((size_t)r * 32 + row) * HDq + c4);
        rv1 = *(const uint2*)(vbh + ((size_t)r * 32 + row) * HDq + c4 + 32);
    }

    for (int i = 0; i < nblk; i++) {
        int r = blist[i];
        __syncthreads();   // previous compute done; tiles free
        {
            const __half2* hk = (const __half2*)&rk;
            #pragma unroll
            for (int j = 0; j < 4; j++) {
                float2 fk = __half22float2(hk[j]);
                kt[row][c8 + 2 * j] = fk.x; kt[row][c8 + 2 * j + 1] = fk.y;
            }
            const __half2* h0 = (const __half2*)&rv0;
            const __half2* h1 = (const __half2*)&rv1;
            #pragma unroll
            for (int j = 0; j < 2; j++) {
                float2 a = __half22float2(h0[j]);
                float2 bb = __half22float2(h1[j]);
                vt2[row][c4 + 2 * j]     = make_float2(a.x, bb.x);
                vt2[row][c4 + 2 * j + 1] = make_float2(a.y, bb.y);
            }
        }
        if (i + 1 < nblk) {
            int rn = blist[i + 1];
            rk  = *(const uint4*)(kbh + ((size_t)rn * 32 + row) * HDq + c8);
            rv0 = *(const uint2*)(vbh + ((size_t)rn * 32 + row) * HDq + c4);
            rv1 = *(const uint2*)(vbh + ((size_t)rn * 32 + row) * HDq + c4 + 32);
        }
        __syncthreads();   // tiles ready

        #pragma unroll
        for (int j = 0; j < 4; j++) {
            if (!((myb[j] >> r) & 1u)) continue;
            int qi = warp * 4 + j;
            // packed dual-accumulator dot product
            uint64_t sc2 = 0;
            #pragma unroll
            for (int d = 0; d < HDq; d += 4) {
                const uint64_t* kv2 = (const uint64_t*)&kt[lane][d];
                const uint64_t* qv2 = (const uint64_t*)&qs[qi][d];
                sc2 = fma2(kv2[0], qv2[0], sc2);
                sc2 = fma2(kv2[1], qv2[1], sc2);
            }
            float2 scp = *(float2*)&sc2;
            float sc = (scp.x + scp.y) * 0.125f;
            float bmax = warp_max(sc);
            float mnew = fmaxf(mr[j], bmax);
            float p = __expf(sc - mnew);
            float scale = __expf(mr[j] - mnew);
            l[j] = l[j] * scale + warp_sum(p);
            cacc[j].x *= scale; cacc[j].y *= scale;
            uint64_t cj = *(uint64_t*)&cacc[j];
            #pragma unroll 8
            for (int t = 0; t < 32; t++) {
                float pj = __shfl_sync(0xffffffffu, p, t);
                float2 pp = make_float2(pj, pj);
                cj = fma2(*(uint64_t*)&pp, *(const uint64_t*)&vt2[t][lane], cj);
            }
            cacc[j] = *(float2*)&cj;
            mr[j] = mnew;
        }
    }

    #pragma unroll
    for (int j = 0; j < 4; j++) {
        int s = s0 + warp * 4 + j;
        float inv = 1.0f / l[j];
        __half* cp = ctx + ((size_t)(b * Sq + s)) * Dq + h * HDq;
        cp[lane] = __float2half_rn(cacc[j].x * inv);
        cp[lane + 32] = __float2half_rn(cacc[j].y * inv);
    }
}

// ---------------- host launch ----------------
extern "C" void kernel_launch(void* const* d_in, const int* in_sizes, int n_in,
                              void* d_out, int out_size) {
    const float* x      = (const float*)d_in[0];
    const float* Wu     = (const float*)d_in[1];
    const float* Wk_sel = (const float*)d_in[2];
    const float* Wq_sel = (const float*)d_in[3];
    const float* Wq     = (const float*)d_in[4];
    const float* Wk     = (const float*)d_in[5];
    const float* Wv     = (const float*)d_in[6];
    const float* Wo     = (const float*)d_in[7];
    float* out = (float*)d_out;

    float *WuT, *WkselT, *part;
    float *pooled, *root, *ksel, *qsel;
    __half *xh, *Wcat_h, *WoT_h, *ctx_h, *q, *k, *v;
    unsigned char* mask;
    cudaGetSymbolAddress((void**)&xh,      g_xh);
    cudaGetSymbolAddress((void**)&WuT,     g_WuT);
    cudaGetSymbolAddress((void**)&WkselT,  g_WkselT);
    cudaGetSymbolAddress((void**)&Wcat_h,  g_Wcat_h);
    cudaGetSymbolAddress((void**)&WoT_h,   g_WoT_h);
    cudaGetSymbolAddress((void**)&part,    g_part);
    cudaGetSymbolAddress((void**)&pooled,  g_pooled);
    cudaGetSymbolAddress((void**)&root,    g_root);
    cudaGetSymbolAddress((void**)&ksel,    g_ksel);
    cudaGetSymbolAddress((void**)&qsel,    g_qsel);
    cudaGetSymbolAddress((void**)&mask,    g_mask);
    cudaGetSymbolAddress((void**)&q,       g_q);
    cudaGetSymbolAddress((void**)&k,       g_k);
    cudaGetSymbolAddress((void**)&v,       g_v);
    cudaGetSymbolAddress((void**)&ctx_h,   g_ctx_h);

    cudaFuncSetAttribute(mma_gemm_h, cudaFuncAttributeMaxDynamicSharedMemorySize, SM_GEMM_BYTES);

    // (1) x -> xh (fp16)
    round_copy_kernel<<<(Mtok * Dq / 4 + 255) / 256, 256>>>(
        (const float4*)x, (__half2*)xh, Mtok * Dq / 4);
    // (2) all weight transposes
    transpose_all_kernel<<<5632, dim3(32, 8)>>>(Wq_sel, Wq, Wk, Wv, Wu, Wo, Wk_sel,
                                                Wcat_h, WuT, WoT_h, WkselT);
    // (3) pooling
    pool_kernel<<<Bq * Rq, 256>>>(x, pooled);
    // (4) fused fp16: [qsel | q | k | v] = xh @ Wcat^T (q/k/v stored fp16)
    mma_gemm_h<<<dim3(NCAT / GBN, Mtok / GBM), 256, SM_GEMM_BYTES>>>(
        xh, Wcat_h, qsel, Mtok, NCAT, Dq, 4, nullptr, q, k, v);
    // (5-6) root = pooled @ Wu (tf32 split-K + rounded reduce)
    mma_gemm_sk<<<dim3(Dq / 64, (Bq * Rq) / 64, 4), 128>>>(pooled, WuT, part, Bq * Rq, Dq, Dq);
    reduce4_kernel<<<(Bq * Rq * Dq / 4 + 255) / 256, 256>>>((const float4*)part, (float4*)root,
                                                            Bq * Rq * Dq / 4, 1);
    // (7-8) ksel = root @ Wk_sel (tf32 split-K + reduce)
    mma_gemm_sk<<<dim3(DAq / 64, (Bq * Rq) / 64, 4), 128>>>(root, WkselT, part, Bq * Rq, DAq, Dq);
    reduce4_kernel<<<(Bq * Rq * DAq / 4 + 255) / 256, 256>>>((const float4*)part, (float4*)ksel,
                                                             Bq * Rq * DAq / 4, 0);
    // (9) selection mask
    select_kernel<<<dim3(Bq, Sq / 8), 256>>>(qsel, ksel, mask);
    // (10) attention (f32x2 packed math)
    attn_kernel<<<dim3(Bq * Hq, Sq / 32), 256>>>(q, k, v, mask, ctx_h);
    // (11) out = ctx_h @ Wo^T + x (fp16 GEMM, fp32 residual)
    mma_gemm_h<<<dim3(Dq / GBN, Mtok / GBM), 256, SM_GEMM_BYTES>>>(
        ctx_h, WoT_h, out, Mtok, Dq, Dq, 2, x, nullptr, nullptr, nullptr);
}

// round 17
// speedup vs baseline: 1.2475x; 1.0140x over previous
#include <cuda_runtime.h>
#include <cuda_fp16.h>
#include <math.h>
#include <stdint.h>

// ---------------- problem constants ----------------
#define Bq 8
#define Sq 1024
#define Dq 1024
#define DAq 256
#define Hq 16
#define HDq 64
#define Rq 32
#define Mtok (Bq*Sq)   // 8192
#define NCAT (DAq + 3*Dq)   // 3328

// ---------------- scratch (device globals; no allocation) ----------------
__device__ __half g_xh[Mtok*Dq];                  // fp16 x
__device__ float g_WuT [Dq*Dq];
__device__ float g_WkselT[DAq*Dq];
__device__ __half g_Wcat_h[NCAT*Dq];              // [qsel|q|k|v] transposed fp16
__device__ __half g_WoT_h[Dq*Dq];
__device__ float g_pooled[Bq*Rq*Dq];
__device__ float g_root  [Bq*Rq*Dq];
__device__ float g_ksel  [Bq*Rq*DAq];
__device__ float g_part[4*256*1024];
__device__ float g_qsel  [Mtok*DAq];
__device__ unsigned char g_mask[Mtok*Rq];
__device__ __half g_q [Mtok*Dq];                  // [B,H,S,64] fp16
__device__ __half g_k [Mtok*Dq];
__device__ __half g_v [Mtok*Dq];
__device__ __half g_ctx_h[Mtok*Dq];               // [B,S,D] fp16

// ---------------- helpers ----------------
__device__ __forceinline__ float rna_tf32(float x) {
    uint32_t r; asm("cvt.rna.tf32.f32 %0, %1;" : "=r"(r) : "f"(x));
    return __uint_as_float(r);
}
__device__ __forceinline__ float warp_max(float v) {
    #pragma unroll
    for (int o = 16; o; o >>= 1) v = fmaxf(v, __shfl_xor_sync(0xffffffffu, v, o));
    return v;
}
__device__ __forceinline__ float warp_sum(float v) {
    #pragma unroll
    for (int o = 16; o; o >>= 1) v += __shfl_xor_sync(0xffffffffu, v, o);
    return v;
}
__device__ __forceinline__ uint32_t smem_u32(const void* p) {
    uint32_t a;
    asm("{ .reg .u64 t; cvta.to.shared.u64 t, %1; cvt.u32.u64 %0, t; }" : "=r"(a) : "l"(p));
    return a;
}
// packed dual-fp32 FMA (sm_100 base ISA, PTX 8.6)
__device__ __forceinline__ uint64_t fma2(uint64_t a, uint64_t b, uint64_t c) {
    asm("fma.rn.f32x2 %0, %1, %2, %3;" : "=l"(c) : "l"(a), "l"(b), "l"(c));
    return c;
}

#define CP16(dst, src) \
    asm volatile("cp.async.cg.shared.global [%0], [%1], 16;" :: "r"(dst), "l"(src))
#define CPCOMMIT() asm volatile("cp.async.commit_group;")
#define CPWAIT(n)  asm volatile("cp.async.wait_group %0;" :: "n"(n))

#define LDSM4(r0, r1, r2, r3, addr) \
    asm volatile("ldmatrix.sync.aligned.m8n8.x4.shared.b16 {%0,%1,%2,%3}, [%4];" \
        : "=r"(r0), "=r"(r1), "=r"(r2), "=r"(r3) : "r"(addr))

__device__ __forceinline__ void mma_tf32(float c[4], const uint32_t a[4], const uint32_t b[2]) {
    asm volatile(
        "mma.sync.aligned.m16n8k8.row.col.f32.tf32.tf32.f32 "
        "{%0,%1,%2,%3}, {%4,%5,%6,%7}, {%8,%9}, {%0,%1,%2,%3};"
        : "+f"(c[0]), "+f"(c[1]), "+f"(c[2]), "+f"(c[3])
        : "r"(a[0]), "r"(a[1]), "r"(a[2]), "r"(a[3]), "r"(b[0]), "r"(b[1]));
}
__device__ __forceinline__ void mma_f16(float c[4], const uint32_t a[4], const uint32_t b[2]) {
    asm volatile(
        "mma.sync.aligned.m16n8k16.row.col.f32.f16.f16.f32 "
        "{%0,%1,%2,%3}, {%4,%5,%6,%7}, {%8,%9}, {%0,%1,%2,%3};"
        : "+f"(c[0]), "+f"(c[1]), "+f"(c[2]), "+f"(c[3])
        : "r"(a[0]), "r"(a[1]), "r"(a[2]), "r"(a[3]), "r"(b[0]), "r"(b[1]));
}

// ---------------- prep kernels ----------------
__global__ void round_copy_kernel(const float4* __restrict__ in, __half2* __restrict__ xh, int n4) {
    int i = blockIdx.x * blockDim.x + threadIdx.x;
    if (i < n4) {
        float4 v = in[i];
        xh[2 * i]     = __floats2half2_rn(v.x, v.y);
        xh[2 * i + 1] = __floats2half2_rn(v.z, v.w);
    }
}

__global__ void transpose_all_kernel(
    const float* __restrict__ Wq_sel, const float* __restrict__ Wq,
    const float* __restrict__ Wk, const float* __restrict__ Wv,
    const float* __restrict__ Wu, const float* __restrict__ Wo,
    const float* __restrict__ Wk_sel,
    __half* __restrict__ Wcat_h, float* __restrict__ WuT,
    __half* __restrict__ WoT_h, float* __restrict__ WkselT)
{
    __shared__ float t[32][33];
    int tix = blockIdx.x;
    const float* W; int Ndim, seg;
    if (tix < 256)       { seg = 0; W = Wq_sel; Ndim = DAq; }
    else if (tix < 1280) { seg = 1; tix -= 256;  W = Wq; Ndim = Dq; }
    else if (tix < 2304) { seg = 2; tix -= 1280; W = Wk; Ndim = Dq; }
    else if (tix < 3328) { seg = 3; tix -= 2304; W = Wv; Ndim = Dq; }
    else if (tix < 4352) { seg = 4; tix -= 3328; W = Wu; Ndim = Dq; }
    else if (tix < 5376) { seg = 5; tix -= 4352; W = Wo; Ndim = Dq; }
    else                 { seg = 6; tix -= 5376; W = Wk_sel; Ndim = DAq; }
    int ntile = Ndim >> 5;
    int n0 = (tix % ntile) * 32, k0 = (tix / ntile) * 32;
    int tx = threadIdx.x, ty = threadIdx.y;
    #pragma unroll
    for (int i = 0; i < 32; i += 8)
        t[ty + i][tx] = W[(size_t)(k0 + ty + i) * Ndim + n0 + tx];
    __syncthreads();
    if (seg <= 3) {
        size_t base = (seg == 0) ? 0 : (size_t)(DAq + (seg - 1) * Dq) * Dq;
        __half* dst = Wcat_h + base;
        #pragma unroll
        for (int i = 0; i < 32; i += 8)
            dst[(size_t)(n0 + ty + i) * Dq + k0 + tx] = __float2half_rn(t[tx][ty + i]);
    } else if (seg == 5) {
        #pragma unroll
        for (int i = 0; i < 32; i += 8)
            WoT_h[(size_t)(n0 + ty + i) * Dq + k0 + tx] = __float2half_rn(t[tx][ty + i]);
    } else {
        float* dst = (seg == 4) ? WuT : WkselT;
        #pragma unroll
        for (int i = 0; i < 32; i += 8)
            dst[(size_t)(n0 + ty + i) * Dq + k0 + tx] = rna_tf32(t[tx][ty + i]);
    }
}

__global__ void pool_kernel(const float* __restrict__ x, float* __restrict__ pooled) {
    int br = blockIdx.x;
    const float* base = x + (size_t)br * 32 * Dq;
    int d4 = threadIdx.x;
    float4 acc = make_float4(0.f, 0.f, 0.f, 0.f);
    #pragma unroll 4
    for (int i = 0; i < 32; i++) {
        float4 v = *(const float4*)(base + (size_t)i * Dq + d4 * 4);
        acc.x += v.x; acc.y += v.y; acc.z += v.z; acc.w += v.w;
    }
    const float s = 1.0f / 32.0f;
    acc.x = rna_tf32(acc.x * s); acc.y = rna_tf32(acc.y * s);
    acc.z = rna_tf32(acc.z * s); acc.w = rna_tf32(acc.w * s);
    *(float4*)(pooled + (size_t)br * Dq + d4 * 4) = acc;
}

// ---------------- fp16 mma.sync GEMM: 128x128, 256 thr, GBK=64 ----------------
#define GBM 128
#define GBN 128
#define GBK 32
#define GBKB 64
#define ROWB 144
#define OP_H_BYTES (128 * ROWB)
#define STAGE_H_BYTES (2 * OP_H_BYTES)
#define SM_GEMM_BYTES (2 * STAGE_H_BYTES) // 73728

__global__ __launch_bounds__(256, 2)
void mma_gemm_h(const __half* __restrict__ A, const __half* __restrict__ Bt,
                float* __restrict__ C, int M, int N, int Kd,
                int mode, const float* __restrict__ resid,
                __half* __restrict__ pq, __half* __restrict__ pk, __half* __restrict__ pv)
{
    extern __shared__ float smf[];
    int tid = threadIdx.x;
    int wid = tid >> 5, lane = tid & 31;
    int warp_row = wid & 1;
    int warp_col = wid >> 1;
    int gr = lane >> 2, gc = lane & 3;
    int bm = blockIdx.y * GBM;
    int bn = blockIdx.x * GBN;

    int sel = lane >> 3, l8 = lane & 7;
    int a_row_off = (sel & 1) * 8 + l8;
    int a_col16 = (sel >> 1) * 16;
    int b_row_off = (sel >> 1) * 8 + l8;
    int b_col16 = (sel & 1) * 16;

    float c[4][4][4];
    #pragma unroll
    for (int f = 0; f < 4; f++)
        #pragma unroll
        for (int g = 0; g < 4; g++)
            #pragma unroll
            for (int i = 0; i < 4; i++) c[f][g][i] = 0.f;

    uint32_t sbase = smem_u32(smf);
    const int NK = Kd / GBKB;

    auto load_stage = [&](int p, int k0) {
        uint32_t Abase = sbase + (uint32_t)(p * STAGE_H_BYTES);
        uint32_t Bbase = Abase + OP_H_BYTES;
        #pragma unroll
        for (int j = 0; j < 4; j++) {
            int idx = tid + j * 256;
            int row = idx >> 3, kc = idx & 7;
            CP16(Abase + (uint32_t)(row * ROWB + kc * 16),
                 A + (size_t)(bm + row) * Kd + k0 + kc * 8);
        }
        #pragma unroll
        for (int j = 0; j < 4; j++) {
            int idx = tid + j * 256;
            int row = idx >> 3, kc = idx & 7;
            CP16(Bbase + (uint32_t)(row * ROWB + kc * 16),
                 Bt + (size_t)(bn + row) * Kd + k0 + kc * 8);
        }
    };

    load_stage(0, 0);
    CPCOMMIT();

    for (int ks = 0; ks < NK; ks++) {
        int p = ks & 1;
        if (ks + 1 < NK) {
            load_stage(p ^ 1, (ks + 1) * GBKB);
            CPCOMMIT();
            CPWAIT(1);
        } else {
            CPWAIT(0);
        }
        __syncthreads();

        uint32_t As = sbase + (uint32_t)(p * STAGE_H_BYTES);
        uint32_t Bs = As + OP_H_BYTES;
        uint32_t aAddr = As + (uint32_t)((warp_row * 64 + a_row_off) * ROWB + a_col16);
        uint32_t bAddr = Bs + (uint32_t)((warp_col * 32 + b_row_off) * ROWB + b_col16);

        #pragma unroll
        for (int kk = 0; kk < 4; kk++) {
            uint32_t a[4][4], b[4][2];
            #pragma unroll
            for (int f = 0; f < 4; f++)
                LDSM4(a[f][0], a[f][1], a[f][2], a[f][3],
                      aAddr + (uint32_t)(f * 16 * ROWB + kk * 32));
            #pragma unroll
            for (int gp = 0; gp < 2; gp++)
                LDSM4(b[2*gp][0], b[2*gp][1], b[2*gp+1][0], b[2*gp+1][1],
                      bAddr + (uint32_t)(gp * 16 * ROWB + kk * 32));
            #pragma unroll
            for (int f = 0; f < 4; f++)
                #pragma unroll
                for (int g = 0; g < 4; g++)
                    mma_f16(c[f][g], a[f], b[g]);
        }
        __syncthreads();
    }

    float* stg = smf;
    #pragma unroll
    for (int f = 0; f < 4; f++)
        #pragma unroll
        for (int g = 0; g < 4; g++) {
            int r0 = warp_row * 64 + f * 16 + gr;
            int c0 = warp_col * 32 + g * 8 + 2 * gc;
            stg[r0 * 132 + c0]           = c[f][g][0];
            stg[r0 * 132 + c0 + 1]       = c[f][g][1];
            stg[(r0 + 8) * 132 + c0]     = c[f][g][2];
            stg[(r0 + 8) * 132 + c0 + 1] = c[f][g][3];
        }
    __syncthreads();

    int ccol = (tid & 31) * 4;
    #pragma unroll 4
    for (int rr = 0; rr < 16; rr++) {
        int r = (tid >> 5) + rr * 8;
        float4 v;
        v.x = stg[r * 132 + ccol + 0];
        v.y = stg[r * 132 + ccol + 1];
        v.z = stg[r * 132 + ccol + 2];
        v.w = stg[r * 132 + ccol + 3];
        int m = bm + r;
        int n = bn + ccol;
        if (mode == 2) {
            float4 rv = *(const float4*)(resid + (size_t)m * N + n);
            v.x += rv.x; v.y += rv.y; v.z += rv.z; v.w += rv.w;
            *(float4*)(C + (size_t)m * N + n) = v;
        } else {
            if (n < DAq) {
                *(float4*)(C + (size_t)m * DAq + n) = v;
            } else {
                int n2 = n - DAq;
                int proj = n2 >> 10, nn = n2 & 1023;
                int h = nn >> 6, hd = nn & 63;
                int b = m >> 10, s = m & 1023;
                __half* P = (proj == 0) ? pq : (proj == 1) ? pk : pv;
                __half2 h01 = __floats2half2_rn(v.x, v.y);
                __half2 h23 = __floats2half2_rn(v.z, v.w);
                uint2 u = make_uint2(*(uint32_t*)&h01, *(uint32_t*)&h23);
                *(uint2*)(P + (((size_t)(b * Hq + h)) * Sq + s) * HDq + hd) = u;
            }
        }
    }
}

// ---------------- split-K small GEMM (tf32, unchanged) ----------------
#define SKLDT 36
#define SK_STAGE (128 * SKLDT)

__global__ __launch_bounds__(128)
void mma_gemm_sk(const float* __restrict__ A, const float* __restrict__ Bt,
                 float* __restrict__ Cpart, int M, int N, int Kd)
{
    __shared__ float smf[2 * SK_STAGE];
    int tid = threadIdx.x;
    int wid = tid >> 5, lane = tid & 31;
    int warp_row = wid & 1;
    int warp_col = wid >> 1;
    int gr = lane >> 2, gc = lane & 3;
    int bm = blockIdx.y * 64;
    int bn = blockIdx.x * 64;
    int kslice = Kd >> 2;
    int kbase = blockIdx.z * kslice;

    int sel = lane >> 3, l8 = lane & 7;
    int a_row_off = (sel & 1) * 8 + l8;
    int a_col_off = (sel >> 1) * 4;
    int b_row_off = (sel >> 1) * 8 + l8;
    int b_col_off = (sel & 1) * 4;

    float c[2][4][4];
    #pragma unroll
    for (int f = 0; f < 2; f++)
        #pragma unroll
        for (int g = 0; g < 4; g++)
            #pragma unroll
            for (int i = 0; i < 4; i++) c[f][g][i] = 0.f;

    uint32_t sbase = smem_u32(smf);
    const int NK = kslice / GBK;

    auto load_stage = [&](int p, int k0) {
        uint32_t Abase = sbase + (uint32_t)(p * SK_STAGE) * 4;
        uint32_t Bbase = Abase + (uint32_t)(64 * SKLDT) * 4;
        #pragma unroll
        for (int j = 0; j < 4; j++) {
            int idx = tid + j * 128;
            int row = idx >> 3, kc = idx & 7;
            CP16(Abase + (uint32_t)(row * SKLDT + kc * 4) * 4,
                 A + (size_t)(bm + row) * Kd + k0 + kc * 4);
        }
        #pragma unroll
        for (int j = 0; j < 4; j++) {
            int idx = tid + j * 128;
            int row = idx >> 3, kc = idx & 7;
            CP16(Bbase + (uint32_t)(row * SKLDT + kc * 4) * 4,
                 Bt + (size_t)(bn + row) * Kd + k0 + kc * 4);
        }
    };

    load_stage(0, kbase);
    CPCOMMIT();

    for (int ks = 0; ks < NK; ks++) {
        int p = ks & 1;
        if (ks + 1 < NK) {
            load_stage(p ^ 1, kbase + (ks + 1) * GBK);
            CPCOMMIT();
            CPWAIT(1);
        } else {
            CPWAIT(0);
        }
        __syncthreads();

        uint32_t As = sbase + (uint32_t)(p * SK_STAGE) * 4;
        uint32_t Bs = As + (uint32_t)(64 * SKLDT) * 4;
        uint32_t aAddr = As + (uint32_t)((warp_row * 32 + a_row_off) * SKLDT + a_col_off) * 4;
        uint32_t bAddr = Bs + (uint32_t)((warp_col * 32 + b_row_off) * SKLDT + b_col_off) * 4;

        #pragma unroll
        for (int kk = 0; kk < 4; kk++) {
            uint32_t a[2][4], b[4][2];
            #pragma unroll
            for (int f = 0; f < 2; f++)
                LDSM4(a[f][0], a[f][1], a[f][2], a[f][3],
                      aAddr + (uint32_t)(f * 16 * SKLDT + kk * 8) * 4);
            #pragma unroll
            for (int gp = 0; gp < 2; gp++)
                LDSM4(b[2*gp][0], b[2*gp][1], b[2*gp+1][0], b[2*gp+1][1],
                      bAddr + (uint32_t)(gp * 16 * SKLDT + kk * 8) * 4);
            #pragma unroll
            for (int f = 0; f < 2; f++)
                #pragma unroll
                for (int g = 0; g < 4; g++)
                    mma_tf32(c[f][g], a[f], b[g]);
        }
        __syncthreads();
    }

    float* Cp = Cpart + (size_t)blockIdx.z * M * N;
    #pragma unroll
    for (int f = 0; f < 2; f++)
        #pragma unroll
        for (int g = 0; g < 4; g++) {
            int r0 = bm + warp_row * 32 + f * 16 + gr;
            int c0 = bn + warp_col * 32 + g * 8 + 2 * gc;
            *(float2*)(Cp + (size_t)r0 * N + c0)       = make_float2(c[f][g][0], c[f][g][1]);
            *(float2*)(Cp + (size_t)(r0 + 8) * N + c0) = make_float2(c[f][g][2], c[f][g][3]);
        }
}

__global__ void reduce4_kernel(const float4* __restrict__ part, float4* __restrict__ dst,
                               int n4, int do_round) {
    int i = blockIdx.x * blockDim.x + threadIdx.x;
    if (i >= n4) return;
    float4 a = part[i], b = part[i + n4], cc = part[i + 2 * n4], d = part[i + 3 * n4];
    float4 v = make_float4(a.x + b.x + cc.x + d.x, a.y + b.y + cc.y + d.y,
                           a.z + b.z + cc.z + d.z, a.w + b.w + cc.w + d.w);
    if (do_round) {
        v.x = rna_tf32(v.x); v.y = rna_tf32(v.y); v.z = rna_tf32(v.z); v.w = rna_tf32(v.w);
    }
    dst[i] = v;
}

// ---------------- block selection ----------------
__global__ __launch_bounds__(256) void select_kernel(
    const float* __restrict__ qsel, const float* __restrict__ ksel,
    unsigned char* __restrict__ mask)
{
    __shared__ float ks[Rq][DAq + 1];
    __shared__ float qrow[8][DAq];
    int b = blockIdx.x;
    int s0 = blockIdx.y * 8;
    int warp = threadIdx.x >> 5, lane = threadIdx.x & 31;
    int s = s0 + warp;

    const float* kp = ksel + (size_t)b * Rq * DAq;
    for (int i = threadIdx.x; i < Rq * DAq; i += 256)
        ks[i >> 8][i & 255] = kp[i];
    const float* qp = qsel + ((size_t)b * Sq + s) * DAq;
    for (int d = lane; d < DAq; d += 32) qrow[warp][d] = qp[d];
    __syncthreads();

    float logit = 0.f;
    #pragma unroll 8
    for (int d = 0; d < DAq; d++)
        logit += qrow[warp][d] * ks[lane][d];
    logit *= 0.0625f;

    float mx = warp_max(logit);
    float e = expf(logit - mx);
    float sum = warp_sum(e);
    float prob = e / sum;
    bool own = (s >> 5) == lane;
    mask[((size_t)b * Sq + s) * Rq + lane] = (prob >= 0.5f || own) ? 1 : 0;
}

// ---------------- block-sparse attention (f32x2 + smem p-broadcast) ----------------
__global__ __launch_bounds__(256) void attn_kernel(
    const __half* __restrict__ Q, const __half* __restrict__ K,
    const __half* __restrict__ V, const unsigned char* __restrict__ mask,
    __half* __restrict__ ctx)
{
    __shared__ float qs[32][68];
    __shared__ float kt[32][68];
    __shared__ float2 vt2[32][36];   // vt2[t][lane] = (v[t][lane], v[t][lane+32])
    __shared__ float ps[8][32];      // per-warp p broadcast buffer
    __shared__ uint32_t qbits[32];
    __shared__ int blist[32];
    __shared__ int nblk_s;

    int bh = blockIdx.x;
    int b = bh >> 4, h = bh & 15;
    int s0 = blockIdx.y * 32;
    int tid = threadIdx.x, warp = tid >> 5, lane = tid & 31;
    int row = tid >> 3, c8 = (tid & 7) * 8, c4 = (tid & 7) * 4;

    // Q tile fp16 -> fp32 smem
    {
        uint4 raw = *(const uint4*)(Q + ((size_t)bh * Sq + s0 + row) * HDq + c8);
        const __half2* hp = (const __half2*)&raw;
        #pragma unroll
        for (int j = 0; j < 4; j++) {
            float2 f = __half22float2(hp[j]);
            qs[row][c8 + 2 * j] = f.x;
            qs[row][c8 + 2 * j + 1] = f.y;
        }
    }

    if (warp == 0) {
        const unsigned char* mrow = mask + ((size_t)b * Sq + s0 + lane) * Rq;
        uint32_t bits = 0;
        #pragma unroll
        for (int r = 0; r < Rq; r++) bits |= (mrow[r] ? 1u : 0u) << r;
        qbits[lane] = bits;
        uint32_t u = bits;
        #pragma unroll
        for (int o = 16; o; o >>= 1) u |= __shfl_xor_sync(0xffffffffu, u, o);
        if (lane == 0) {
            int n = 0;
            for (int r = 0; r < 32; r++)
                if ((u >> r) & 1u) blist[n++] = r;
            nblk_s = n;
        }
    }
    __syncthreads();
    int nblk = nblk_s;
    uint32_t myb[4];
    #pragma unroll
    for (int j = 0; j < 4; j++) myb[j] = qbits[warp * 4 + j];

    float mr[4], l[4];
    float2 cacc[4];
    #pragma unroll
    for (int j = 0; j < 4; j++) { mr[j] = -INFINITY; l[j] = 0.f; cacc[j] = make_float2(0.f, 0.f); }

    const __half* kbh = K + (size_t)bh * Sq * HDq;
    const __half* vbh = V + (size_t)bh * Sq * HDq;

    // prefetch block 0
    uint4 rk; uint2 rv0, rv1;
    {
        int r = blist[0];
        rk  = *(const uint4*)(kbh + ((size_t)r * 32 + row) * HDq + c8);
        rv0 = *(const uint2*)(vbh + ((size_t)r * 32 + row) * HDq + c4);
        rv1 = *(const uint2*)(vbh + ((size_t)r * 32 + row) * HDq + c4 + 32);
    }

    for (int i = 0; i < nblk; i++) {
        int r = blist[i];
        __syncthreads();
        {
            const __half2* hk = (const __half2*)&rk;
            #pragma unroll
            for (int j = 0; j < 4; j++) {
                float2 fk = __half22float2(hk[j]);
                kt[row][c8 + 2 * j] = fk.x; kt[row][c8 + 2 * j + 1] = fk.y;
            }
            const __half2* h0 = (const __half2*)&rv0;
            const __half2* h1 = (const __half2*)&rv1;
            #pragma unroll
            for (int j = 0; j < 2; j++) {
                float2 a = __half22float2(h0[j]);
                float2 bb = __half22float2(h1[j]);
                vt2[row][c4 + 2 * j]     = make_float2(a.x, bb.x);
                vt2[row][c4 + 2 * j + 1] = make_float2(a.y, bb.y);
            }
        }
        if (i + 1 < nblk) {
            int rn = blist[i + 1];
            rk  = *(const uint4*)(kbh + ((size_t)rn * 32 + row) * HDq + c8);
            rv0 = *(const uint2*)(vbh + ((size_t)rn * 32 + row) * HDq + c4);
            rv1 = *(const uint2*)(vbh + ((size_t)rn * 32 + row) * HDq + c4 + 32);
        }
        __syncthreads();

        #pragma unroll
        for (int j = 0; j < 4; j++) {
            if (!((myb[j] >> r) & 1u)) continue;
            int qi = warp * 4 + j;
            uint64_t sc2 = 0;
            #pragma unroll
            for (int d = 0; d < HDq; d += 4) {
                const uint64_t* kv2 = (const uint64_t*)&kt[lane][d];
                const uint64_t* qv2 = (const uint64_t*)&qs[qi][d];
                sc2 = fma2(kv2[0], qv2[0], sc2);
                sc2 = fma2(kv2[1], qv2[1], sc2);
            }
            float2 scp = *(float2*)&sc2;
            float sc = (scp.x + scp.y) * 0.125f;
            float bmax = warp_max(sc);
            float mnew = fmaxf(mr[j], bmax);
            float p = __expf(sc - mnew);
            float scale = __expf(mr[j] - mnew);
            l[j] = l[j] * scale + warp_sum(p);
            // stage p in smem: lane owns key=lane
            ps[warp][lane] = p;
            __syncwarp();
            cacc[j].x *= scale; cacc[j].y *= scale;
            uint64_t cj = *(uint64_t*)&cacc[j];
            #pragma unroll
            for (int t = 0; t < 32; t += 4) {
                float4 pv = *(const float4*)&ps[warp][t];
                float2 p0 = make_float2(pv.x, pv.x);
                float2 p1 = make_float2(pv.y, pv.y);
                float2 p2 = make_float2(pv.z, pv.z);
                float2 p3 = make_float2(pv.w, pv.w);
                cj = fma2(*(uint64_t*)&p0, *(const uint64_t*)&vt2[t][lane], cj);
                cj = fma2(*(uint64_t*)&p1, *(const uint64_t*)&vt2[t + 1][lane], cj);
                cj = fma2(*(uint64_t*)&p2, *(const uint64_t*)&vt2[t + 2][lane], cj);
                cj = fma2(*(uint64_t*)&p3, *(const uint64_t*)&vt2[t + 3][lane], cj);
            }
            cacc[j] = *(float2*)&cj;
            mr[j] = mnew;
        }
    }

    #pragma unroll
    for (int j = 0; j < 4; j++) {
        int s = s0 + warp * 4 + j;
        float inv = 1.0f / l[j];
        __half* cp = ctx + ((size_t)(b * Sq + s)) * Dq + h * HDq;
        cp[lane] = __float2half_rn(cacc[j].x * inv);
        cp[lane + 32] = __float2half_rn(cacc[j].y * inv);
    }
}

// ---------------- host launch ----------------
extern "C" void kernel_launch(void* const* d_in, const int* in_sizes, int n_in,
                              void* d_out, int out_size) {
    const float* x      = (const float*)d_in[0];
    const float* Wu     = (const float*)d_in[1];
    const float* Wk_sel = (const float*)d_in[2];
    const float* Wq_sel = (const float*)d_in[3];
    const float* Wq     = (const float*)d_in[4];
    const float* Wk     = (const float*)d_in[5];
    const float* Wv     = (const float*)d_in[6];
    const float* Wo     = (const float*)d_in[7];
    float* out = (float*)d_out;

    float *WuT, *WkselT, *part;
    float *pooled, *root, *ksel, *qsel;
    __half *xh, *Wcat_h, *WoT_h, *ctx_h, *q, *k, *v;
    unsigned char* mask;
    cudaGetSymbolAddress((void**)&xh,      g_xh);
    cudaGetSymbolAddress((void**)&WuT,     g_WuT);
    cudaGetSymbolAddress((void**)&WkselT,  g_WkselT);
    cudaGetSymbolAddress((void**)&Wcat_h,  g_Wcat_h);
    cudaGetSymbolAddress((void**)&WoT_h,   g_WoT_h);
    cudaGetSymbolAddress((void**)&part,    g_part);
    cudaGetSymbolAddress((void**)&pooled,  g_pooled);
    cudaGetSymbolAddress((void**)&root,    g_root);
    cudaGetSymbolAddress((void**)&ksel,    g_ksel);
    cudaGetSymbolAddress((void**)&qsel,    g_qsel);
    cudaGetSymbolAddress((void**)&mask,    g_mask);
    cudaGetSymbolAddress((void**)&q,       g_q);
    cudaGetSymbolAddress((void**)&k,       g_k);
    cudaGetSymbolAddress((void**)&v,       g_v);
    cudaGetSymbolAddress((void**)&ctx_h,   g_ctx_h);

    cudaFuncSetAttribute(mma_gemm_h, cudaFuncAttributeMaxDynamicSharedMemorySize, SM_GEMM_BYTES);

    // (1) x -> xh (fp16)
    round_copy_kernel<<<(Mtok * Dq / 4 + 255) / 256, 256>>>(
        (const float4*)x, (__half2*)xh, Mtok * Dq / 4);
    // (2) all weight transposes
    transpose_all_kernel<<<5632, dim3(32, 8)>>>(Wq_sel, Wq, Wk, Wv, Wu, Wo, Wk_sel,
                                                Wcat_h, WuT, WoT_h, WkselT);
    // (3) pooling
    pool_kernel<<<Bq * Rq, 256>>>(x, pooled);
    // (4) fused fp16: [qsel | q | k | v] = xh @ Wcat^T (q/k/v stored fp16)
    mma_gemm_h<<<dim3(NCAT / GBN, Mtok / GBM), 256, SM_GEMM_BYTES>>>(
        xh, Wcat_h, qsel, Mtok, NCAT, Dq, 4, nullptr, q, k, v);
    // (5-6) root = pooled @ Wu (tf32 split-K + rounded reduce)
    mma_gemm_sk<<<dim3(Dq / 64, (Bq * Rq) / 64, 4), 128>>>(pooled, WuT, part, Bq * Rq, Dq, Dq);
    reduce4_kernel<<<(Bq * Rq * Dq / 4 + 255) / 256, 256>>>((const float4*)part, (float4*)root,
                                                            Bq * Rq * Dq / 4, 1);
    // (7-8) ksel = root @ Wk_sel (tf32 split-K + reduce)
    mma_gemm_sk<<<dim3(DAq / 64, (Bq * Rq) / 64, 4), 128>>>(root, WkselT, part, Bq * Rq, DAq, Dq);
    reduce4_kernel<<<(Bq * Rq * DAq / 4 + 255) / 256, 256>>>((const float4*)part, (float4*)ksel,
                                                             Bq * Rq * DAq / 4, 0);
    // (9) selection mask
    select_kernel<<<dim3(Bq, Sq / 8), 256>>>(qsel, ksel, mask);
    // (10) attention (f32x2 + smem p-broadcast)
    attn_kernel<<<dim3(Bq * Hq, Sq / 32), 256>>>(q, k, v, mask, ctx_h);
    // (11) out = ctx_h @ Wo^T + x (fp16 GEMM, fp32 residual)
    mma_gemm_h<<<dim3(Dq / GBN, Mtok / GBM), 256, SM_GEMM_BYTES>>>(
        ctx_h, WoT_h, out, Mtok, Dq, Dq, 2, x, nullptr, nullptr, nullptr);
}